// round 11
// baseline (speedup 1.0000x reference)
#include <cuda_runtime.h>
#include <cstdint>

#define VOCAB 50000
#define EMBD  300
#define HID   64
#define G4    256      // 4*H
#define D2    128      // 2*H
#define BATCH 128
#define TBODY 512
#define TPUN  256

// ---------------- scratch (static device arrays: allocation-free) ----------------
__device__ float    g_tbl[(size_t)4 * VOCAB * G4];          // 204.8 MB gate tables
__device__ float    g_bodyM[(size_t)BATCH * TBODY * D2];    // 33.5 MB
__device__ float    g_punM[(size_t)BATCH * TPUN * D2];      // 16.8 MB
__device__ unsigned g_rowmax[BATCH * TBODY];                // ordered-int encoded
__device__ unsigned g_colmax[BATCH * TPUN];                 // ordered-int encoded
__device__ int      g_flag[2][VOCAB];                       // 0 body, 1 pun
__device__ int      g_list[2][VOCAB];
__device__ int      g_cnt[2];

// ---------------- helpers ----------------
__device__ __forceinline__ unsigned enc_f(float f) {
    unsigned u = __float_as_uint(f);
    return (u & 0x80000000u) ? ~u : (u | 0x80000000u);
}
__device__ __forceinline__ float dec_f(unsigned u) {
    return __uint_as_float((u & 0x80000000u) ? (u ^ 0x80000000u) : ~u);
}
// packed fp32x2 FMA (sm_100+): 2 FMA per lane per issue
__device__ __forceinline__ unsigned long long ffma2(unsigned long long a,
                                                    unsigned long long b,
                                                    unsigned long long c) {
    unsigned long long d;
    asm("fma.rn.f32x2 %0, %1, %2, %3;" : "=l"(d) : "l"(a), "l"(b), "l"(c));
    return d;
}
__device__ __forceinline__ unsigned long long pk2(float x) {
    unsigned long long r;
    asm("mov.b64 %0, {%1, %1};" : "=l"(r) : "f"(x));
    return r;
}
__device__ __forceinline__ float2 up2(unsigned long long p) {
    float2 r;
    asm("mov.b64 {%0, %1}, %2;" : "=f"(r.x), "=f"(r.y) : "l"(p));
    return r;
}

// ---------------- kernel 0: zero flags/counters + encoded-max arrays ----------------
__global__ void zero_kernel() {
    int i = blockIdx.x * blockDim.x + threadIdx.x;   // grid covers 65536
    if (i < VOCAB) { g_flag[0][i] = 0; g_flag[1][i] = 0; }
    if (i == 0) { g_cnt[0] = 0; g_cnt[1] = 0; }
    if (i < BATCH * TBODY) g_rowmax[i] = 0u;
    if (i < BATCH * TPUN)  g_colmax[i] = 0u;
}

// ---------------- kernel 0b: mark used vocab ids, warp-aggregated compaction ------
__global__ void mark_kernel(const int* __restrict__ body_idx,
                            const int* __restrict__ pun_idx) {
    int i = blockIdx.x * blockDim.x + threadIdx.x;   // 98304 threads
    int which, v;
    if (i < BATCH * TBODY) { which = 0; v = body_idx[i]; }
    else                   { which = 1; v = pun_idx[i - BATCH * TBODY]; }
    // each warp is entirely one type (boundary 65536 is warp-aligned)
    bool isnew = (atomicExch(&g_flag[which][v], 1) == 0);
    unsigned mask = __ballot_sync(0xFFFFFFFFu, isnew);
    int n = __popc(mask);
    if (n) {
        int lane = threadIdx.x & 31;
        int leader = __ffs(mask) - 1;
        int base = 0;
        if (lane == leader) base = atomicAdd(&g_cnt[which], n);
        base = __shfl_sync(0xFFFFFFFFu, base, leader);
        if (isnew) g_list[which][base + __popc(mask & ((1u << lane) - 1))] = v;
    }
}

// ---------------- kernel 1: gate-table GEMM over USED vocab rows ------------------
// grid (391, 4, 2): x = m-block over used list, y = 128-col block of fused N=512
// (y>>1 = direction, y&1 = col half), z = text type (0 body, 1 pun).
// Tile 128x128, BK=20, 256 thr, 8x8 FFMA2 micro, double-buffered smem,
// A-side stored pre-duplicated as f32x2 in smem (no pk2 MOVs in inner loop).
#define BM 128
#define BN 128
#define BK 20
__global__ void __launch_bounds__(256, 2) gemm_tbl_kernel(
    const float* __restrict__ emb,
    const float* __restrict__ W0, const float* __restrict__ W1,
    const float* __restrict__ W2, const float* __restrict__ W3,
    const float* __restrict__ B0, const float* __restrict__ B1,
    const float* __restrict__ B2, const float* __restrict__ B3)
{
    int z = blockIdx.z;
    int cnt = g_cnt[z];
    int m0 = blockIdx.x * BM;
    if (m0 >= cnt) return;
    int y = blockIdx.y;
    int dir = y >> 1;
    int n0 = (y & 1) * 128;          // col offset within this direction's 256
    int seg = z * 2 + dir;
    const float* W    = (seg == 0) ? W0 : (seg == 1) ? W1 : (seg == 2) ? W2 : W3;
    const float* bias = (seg == 0) ? B0 : (seg == 1) ? B1 : (seg == 2) ? B2 : B3;
    float* out = g_tbl + (size_t)seg * VOCAB * G4;

    __shared__ __align__(16) unsigned long long As[2][BK][BM + 2];  // dup f32x2
    __shared__ __align__(16) float Bs[2][BK][BN + 4];
    __shared__ int ids[BM];

    int tid = threadIdx.x;
    int tx = tid & 15, ty = tid >> 4;

    if (tid < BM) ids[tid] = (m0 + tid < cnt) ? g_list[z][m0 + tid] : 0;
    __syncthreads();

    unsigned long long acc[8][4];
#pragma unroll
    for (int i = 0; i < 8; i++)
#pragma unroll
        for (int j = 0; j < 4; j++) acc[i][j] = 0ull;

    float ra[10], rb[10];
#pragma unroll
    for (int it = 0; it < 10; it++) {
        int l = tid + 256 * it;
        int r = l / BK, kk = l - r * BK;
        ra[it] = emb[(size_t)ids[r] * EMBD + kk];
        rb[it] = W[(size_t)(n0 + r) * EMBD + kk];
    }

    for (int ks = 0; ks < 15; ks++) {
        int buf = ks & 1;
#pragma unroll
        for (int it = 0; it < 10; it++) {
            int l = tid + 256 * it;
            int r = l / BK, kk = l - r * BK;
            As[buf][kk][r] = pk2(ra[it]);
            Bs[buf][kk][r] = rb[it];
        }
        __syncthreads();
        if (ks < 14) {
            int k0 = (ks + 1) * BK;
#pragma unroll
            for (int it = 0; it < 10; it++) {
                int l = tid + 256 * it;
                int r = l / BK, kk = l - r * BK;
                ra[it] = emb[(size_t)ids[r] * EMBD + k0 + kk];
                rb[it] = W[(size_t)(n0 + r) * EMBD + k0 + kk];
            }
        }
#pragma unroll
        for (int kk = 0; kk < BK; kk++) {
            ulonglong2 a01 = *(const ulonglong2*)&As[buf][kk][ty * 4];
            ulonglong2 a23 = *(const ulonglong2*)&As[buf][kk][ty * 4 + 2];
            ulonglong2 a45 = *(const ulonglong2*)&As[buf][kk][64 + ty * 4];
            ulonglong2 a67 = *(const ulonglong2*)&As[buf][kk][64 + ty * 4 + 2];
            ulonglong2 b0 = *(const ulonglong2*)&Bs[buf][kk][tx * 4];
            ulonglong2 b1 = *(const ulonglong2*)&Bs[buf][kk][64 + tx * 4];
            unsigned long long ap[8];
            ap[0] = a01.x; ap[1] = a01.y; ap[2] = a23.x; ap[3] = a23.y;
            ap[4] = a45.x; ap[5] = a45.y; ap[6] = a67.x; ap[7] = a67.y;
#pragma unroll
            for (int i = 0; i < 8; i++) {
                acc[i][0] = ffma2(ap[i], b0.x, acc[i][0]);
                acc[i][1] = ffma2(ap[i], b0.y, acc[i][1]);
                acc[i][2] = ffma2(ap[i], b1.x, acc[i][2]);
                acc[i][3] = ffma2(ap[i], b1.y, acc[i][3]);
            }
        }
    }

    float4 bs0 = *(const float4*)&bias[n0 + tx * 4];
    float4 bs1 = *(const float4*)&bias[n0 + 64 + tx * 4];
#pragma unroll
    for (int i = 0; i < 8; i++) {
        int r = ids[ty * 4 + (i & 3) + (i >> 2) * 64];
        float2 v0 = up2(acc[i][0]), v1 = up2(acc[i][1]);
        float2 v2 = up2(acc[i][2]), v3 = up2(acc[i][3]);
        float4 o0 = make_float4(v0.x + bs0.x, v0.y + bs0.y, v1.x + bs0.z, v1.y + bs0.w);
        float4 o1 = make_float4(v2.x + bs1.x, v2.y + bs1.y, v3.x + bs1.z, v3.y + bs1.w);
        *(float4*)&out[(size_t)r * G4 + n0 + tx * 4] = o0;
        *(float4*)&out[(size_t)r * G4 + n0 + 64 + tx * 4] = o1;
    }
}

// ---------------- kernel 2: LSTM, split-dot 512-thread blocks ---------------------
// 512 blocks (puns first), 512 thr, __launch_bounds__(512,2) -> <=64 regs ->
// 2 blocks/SM = 32 warps/SM (2x R9 residency; lstm was warp-starved at issue=48%).
// Warp owns 4 units; lane = u_local*8 + gc*2 + half. Each thread: 32-wide half-dot
// (16 Whh pairs in regs, 8 LDS.128 of h), halves combined via shfl_xor(1),
// gates combined via 3 intra-group shuffles. One __syncthreads/step; hs ping-pong.
__global__ void __launch_bounds__(512, 2) lstm_kernel(
    const int* __restrict__ body_idx, const int* __restrict__ pun_idx,
    const float* __restrict__ Whh0, const float* __restrict__ Whh1,
    const float* __restrict__ Whh2, const float* __restrict__ Whh3)
{
    int blk = blockIdx.x;
    int seg = (blk >> 7) ^ 2;        // schedule puns (short) first
    int b   = blk & 127;
    bool isBody = (seg < 2);
    bool isFwd  = ((seg & 1) == 0);
    int T = isBody ? TBODY : TPUN;
    const int* idx = isBody ? (body_idx + b * TBODY) : (pun_idx + b * TPUN);
    const float* Whh = (seg == 0) ? Whh0 : (seg == 1) ? Whh1 : (seg == 2) ? Whh2 : Whh3;
    const float* tbl = g_tbl + (size_t)seg * VOCAB * G4;
    float* out = isBody ? (g_bodyM + (size_t)b * TBODY * D2)
                        : (g_punM  + (size_t)b * TPUN  * D2);
    int dirOff = isFwd ? 0 : HID;

    __shared__ int idx_s[TBODY];
    __shared__ __align__(16) float hs[2][HID];
    __shared__ int len_s;

    int tid  = threadIdx.x;
    int lane = tid & 31;
    int warp = tid >> 5;                 // 0..15
    int off  = lane & 7;                 // within 8-lane unit group
    int half = off & 1;                  // k-half: 0 -> h[0:32), 1 -> h[32:64)
    int gc   = off >> 1;                 // gate class: 0=i,1=f,2=g,3=o
    int u    = (warp << 2) | (lane >> 3);// hidden unit 0..63
    int r    = gc * HID + u;             // gate row 0..255
    int kh   = half * 32;                // k-offset of this half

    if (tid == 0) len_s = 0;
    if (tid < HID) { hs[0][tid] = 0.f; hs[1][tid] = 0.f; }
    __syncthreads();

    int cnt = 0;
    for (int t = tid; t < T; t += 512) {
        int v = idx[t];
        idx_s[t] = v;
        cnt += (v != 0);
    }
#pragma unroll
    for (int o = 16; o; o >>= 1) cnt += __shfl_xor_sync(0xFFFFFFFFu, cnt, o);
    if (lane == 0) atomicAdd(&len_s, cnt);
    __syncthreads();
    int len = len_s;

    // 16 packed Whh pairs for this (row, half): floats [kh, kh+32)
    unsigned long long wp[16];
    {
        const unsigned long long* wr =
            (const unsigned long long*)(Whh + (size_t)r * HID + kh);
#pragma unroll
        for (int j = 0; j < 16; j++) wp[j] = wr[j];
    }

    float c = 0.f;
    float x1 = 0.f, x2 = 0.f;
    if (half == 0) {
        if (len > 0) x1 = tbl[(size_t)idx_s[isFwd ? 0 : (len - 1)] * G4 + r];
        if (len > 1) x2 = tbl[(size_t)idx_s[isFwd ? 1 : (len - 2)] * G4 + r];
    }

    for (int t = 0; t < len; t++) {
        float xs = x1;
        x1 = x2;
        if (t + 2 < len && half == 0) {
            int p2 = isFwd ? (t + 2) : (len - 3 - t);
            x2 = tbl[(size_t)idx_s[p2] * G4 + r];
        }
        const ulonglong2* hp = (const ulonglong2*)(hs[t & 1] + kh);  // 8 x 16B
        unsigned long long a0 = 0ull, a1 = 0ull, a2 = 0ull, a3 = 0ull;
#pragma unroll
        for (int jj = 0; jj < 4; jj++) {
            ulonglong2 hA = hp[2 * jj];
            ulonglong2 hB = hp[2 * jj + 1];
            a0 = ffma2(wp[4 * jj + 0], hA.x, a0);
            a1 = ffma2(wp[4 * jj + 1], hA.y, a1);
            a2 = ffma2(wp[4 * jj + 2], hB.x, a2);
            a3 = ffma2(wp[4 * jj + 3], hB.y, a3);
        }
        float2 s0 = up2(a0), s1 = up2(a1), s2 = up2(a2), s3 = up2(a3);
        float partial = ((s0.x + s0.y) + (s1.x + s1.y))
                      + ((s2.x + s2.y) + (s3.x + s3.y));
        if (half == 0) partial += xs;
        float tot = partial + __shfl_xor_sync(0xFFFFFFFFu, partial, 1);
        // gate order i,f,g,o ; g-gate tanh, others sigmoid
        float act = (gc == 2) ? tanhf(tot) : 1.f / (1.f + __expf(-tot));
        int gbase = lane & 24;
        float fA = __shfl_sync(0xFFFFFFFFu, act, gbase | ((off + 2) & 7));
        float gA = __shfl_sync(0xFFFFFFFFu, act, gbase | ((off + 4) & 7));
        float oA = __shfl_sync(0xFFFFFFFFu, act, gbase | ((off + 6) & 7));
        if (gc == 0) {
            c = fA * c + act * gA;          // act = i-gate (both halves identical)
            float h = oA * tanhf(c);
            if (half == 0) {
                hs[(t + 1) & 1][u] = h;
                int pos = isFwd ? t : (len - 1 - t);
                out[(size_t)pos * D2 + dirOff + u] = h;
            }
        }
        __syncthreads();
    }
    for (int l = tid; l < (T - len) * HID; l += 512) {
        int tpos = len + l / HID;
        int j = l - (l / HID) * HID;
        out[(size_t)tpos * D2 + dirOff + j] = 0.f;
    }
}

// ---------------- kernel 3: alignment maxes (double-buffered GEMM form) ----------------
// grid = 128 batches * 4 t-chunks * 2 p-chunks = 1024 blocks, 256 thr.
// Tile 128t x 128p, BK=16 over d; body side stored pre-duplicated f32x2 in smem.
#define ABK 16
__global__ void __launch_bounds__(256, 2) align_kernel(const float* __restrict__ w_u)
{
    int bx = blockIdx.x;
    int b  = bx >> 3;
    int tc = (bx >> 1) & 3;
    int pc = bx & 1;
    int t0 = tc * 128;
    int p0 = pc * 128;
    const float* bodyM = g_bodyM + (size_t)b * TBODY * D2;
    const float* punM  = g_punM  + (size_t)b * TPUN  * D2;

    __shared__ __align__(16) unsigned long long Bsu[2][ABK][130];  // [d][t] dup, w3 applied
    __shared__ __align__(16) float Ps[2][ABK][132];                // [d][p]
    __shared__ float a1s[128], a2s[128];
    __shared__ unsigned rms[128], cms[128];

    int tid = threadIdx.x;
    int tx = tid & 15, ty = tid >> 4;
    int warp = tid >> 5, lane = tid & 31;
    int q  = tid & 3;        // d-quad within chunk
    int rr = tid >> 2;       // row 0..63 (+64 on second pass)

    if (tid < 128) { rms[tid] = 0u; cms[tid] = 0u; }
    __syncthreads();

    // a1 (w1·body row) for local 128 t rows; a2 (w2·pun row) for local 128 p rows
    for (int r = warp; r < 128; r += 8) {
        const float* row = bodyM + (size_t)(t0 + r) * D2;
        float s = 0.f;
        for (int d = lane; d < D2; d += 32) s += row[d] * w_u[d];
#pragma unroll
        for (int o = 16; o; o >>= 1) s += __shfl_xor_sync(0xFFFFFFFFu, s, o);
        if (lane == 0) a1s[r] = s;
    }
    for (int r = warp; r < 128; r += 8) {
        const float* row = punM + (size_t)(p0 + r) * D2;
        float s = 0.f;
        for (int d = lane; d < D2; d += 32) s += row[d] * w_u[D2 + d];
#pragma unroll
        for (int o = 16; o; o >>= 1) s += __shfl_xor_sync(0xFFFFFFFFu, s, o);
        if (lane == 0) a2s[r] = s;
    }

    unsigned long long acc[8][4];
#pragma unroll
    for (int i = 0; i < 8; i++)
#pragma unroll
        for (int j = 0; j < 4; j++) acc[i][j] = 0ull;

    // prefetch chunk 0
    float4 bv[2], pv[2];
    {
        float4 w3v = *(const float4*)&w_u[2 * D2 + 4 * q];
#pragma unroll
        for (int i = 0; i < 2; i++) {
            int r = rr + 64 * i;
            float4 v = *(const float4*)&bodyM[(size_t)(t0 + r) * D2 + 4 * q];
            bv[i] = make_float4(v.x * w3v.x, v.y * w3v.y, v.z * w3v.z, v.w * w3v.w);
            pv[i] = *(const float4*)&punM[(size_t)(p0 + r) * D2 + 4 * q];
        }
    }

    for (int kc = 0; kc < 8; kc++) {
        int buf = kc & 1;
#pragma unroll
        for (int i = 0; i < 2; i++) {
            int r = rr + 64 * i;
            Bsu[buf][4 * q + 0][r] = pk2(bv[i].x);
            Bsu[buf][4 * q + 1][r] = pk2(bv[i].y);
            Bsu[buf][4 * q + 2][r] = pk2(bv[i].z);
            Bsu[buf][4 * q + 3][r] = pk2(bv[i].w);
            Ps[buf][4 * q + 0][r] = pv[i].x;
            Ps[buf][4 * q + 1][r] = pv[i].y;
            Ps[buf][4 * q + 2][r] = pv[i].z;
            Ps[buf][4 * q + 3][r] = pv[i].w;
        }
        __syncthreads();
        if (kc < 7) {
            int d0 = (kc + 1) * ABK;
            float4 w3v = *(const float4*)&w_u[2 * D2 + d0 + 4 * q];
#pragma unroll
            for (int i = 0; i < 2; i++) {
                int r = rr + 64 * i;
                float4 v = *(const float4*)&bodyM[(size_t)(t0 + r) * D2 + d0 + 4 * q];
                bv[i] = make_float4(v.x * w3v.x, v.y * w3v.y, v.z * w3v.z, v.w * w3v.w);
                pv[i] = *(const float4*)&punM[(size_t)(p0 + r) * D2 + d0 + 4 * q];
            }
        }
#pragma unroll
        for (int d = 0; d < ABK; d++) {
            ulonglong2 a01 = *(const ulonglong2*)&Bsu[buf][d][ty * 4];
            ulonglong2 a23 = *(const ulonglong2*)&Bsu[buf][d][ty * 4 + 2];
            ulonglong2 a45 = *(const ulonglong2*)&Bsu[buf][d][64 + ty * 4];
            ulonglong2 a67 = *(const ulonglong2*)&Bsu[buf][d][64 + ty * 4 + 2];
            ulonglong2 b0 = *(const ulonglong2*)&Ps[buf][d][tx * 4];
            ulonglong2 b1 = *(const ulonglong2*)&Ps[buf][d][64 + tx * 4];
            unsigned long long ap[8];
            ap[0] = a01.x; ap[1] = a01.y; ap[2] = a23.x; ap[3] = a23.y;
            ap[4] = a45.x; ap[5] = a45.y; ap[6] = a67.x; ap[7] = a67.y;
#pragma unroll
            for (int i = 0; i < 8; i++) {
                acc[i][0] = ffma2(ap[i], b0.x, acc[i][0]);
                acc[i][1] = ffma2(ap[i], b0.y, acc[i][1]);
                acc[i][2] = ffma2(ap[i], b1.x, acc[i][2]);
                acc[i][3] = ffma2(ap[i], b1.y, acc[i][3]);
            }
        }
    }

    // combine with a1/a2, reduce maxes
    float rmax[8], cmax[8];
#pragma unroll
    for (int i = 0; i < 8; i++) { rmax[i] = -1e30f; cmax[i] = -1e30f; }
#pragma unroll
    for (int i = 0; i < 8; i++) {
        int trow = ty * 4 + (i & 3) + (i >> 2) * 64;
        float a1v = a1s[trow];
#pragma unroll
        for (int jp = 0; jp < 4; jp++) {
            float2 v = up2(acc[i][jp]);
            int c0 = tx * 4 + (jp >> 1) * 64 + (jp & 1) * 2;
            float v0 = v.x + a1v + a2s[c0];
            float v1 = v.y + a1v + a2s[c0 + 1];
            rmax[i] = fmaxf(rmax[i], fmaxf(v0, v1));
            int jj = (jp >> 1) * 4 + (jp & 1) * 2;
            cmax[jj]     = fmaxf(cmax[jj], v0);
            cmax[jj + 1] = fmaxf(cmax[jj + 1], v1);
        }
    }
#pragma unroll
    for (int i = 0; i < 8; i++) {
        int trow = ty * 4 + (i & 3) + (i >> 2) * 64;
        atomicMax(&rms[trow], enc_f(rmax[i]));
    }
#pragma unroll
    for (int j = 0; j < 8; j++) {
        int col = tx * 4 + (j >> 2) * 64 + (j & 3);
        atomicMax(&cms[col], enc_f(cmax[j]));
    }
    __syncthreads();

    if (tid < 128) {
        atomicMax(&g_rowmax[b * TBODY + t0 + tid], rms[tid]);
        atomicMax(&g_colmax[b * TPUN + p0 + tid], cms[tid]);
    }
}

// ---------------- kernel 4: softmaxes + weighted sums + final linear ----------------
__global__ void __launch_bounds__(256) final_kernel(
    const float* __restrict__ Wd, const float* __restrict__ bd,
    float* __restrict__ outp)
{
    int b = blockIdx.x;
    int tid = threadIdx.x;
    int lane = tid & 31, warp = tid >> 5;

    __shared__ float attb[TBODY];
    __shared__ float attp[TPUN];
    __shared__ float feat[G4];
    __shared__ float sred[8];

    // softmax over rowmax[512]
    float v0 = dec_f(g_rowmax[b * TBODY + tid]);
    float v1 = dec_f(g_rowmax[b * TBODY + 256 + tid]);
    float m = fmaxf(v0, v1);
#pragma unroll
    for (int o = 16; o; o >>= 1) m = fmaxf(m, __shfl_xor_sync(0xFFFFFFFFu, m, o));
    if (lane == 0) sred[warp] = m;
    __syncthreads();
    float M = sred[0];
#pragma unroll
    for (int w = 1; w < 8; w++) M = fmaxf(M, sred[w]);
    __syncthreads();
    float e0 = __expf(v0 - M), e1 = __expf(v1 - M);
    float ss = e0 + e1;
#pragma unroll
    for (int o = 16; o; o >>= 1) ss += __shfl_xor_sync(0xFFFFFFFFu, ss, o);
    if (lane == 0) sred[warp] = ss;
    __syncthreads();
    float S = 0.f;
#pragma unroll
    for (int w = 0; w < 8; w++) S += sred[w];
    __syncthreads();
    attb[tid] = e0 / S;
    attb[256 + tid] = e1 / S;

    // softmax over colmax[256]
    float u = dec_f(g_colmax[b * TPUN + tid]);
    float m2 = u;
#pragma unroll
    for (int o = 16; o; o >>= 1) m2 = fmaxf(m2, __shfl_xor_sync(0xFFFFFFFFu, m2, o));
    if (lane == 0) sred[warp] = m2;
    __syncthreads();
    float M2 = sred[0];
#pragma unroll
    for (int w = 1; w < 8; w++) M2 = fmaxf(M2, sred[w]);
    __syncthreads();
    float e2 = __expf(u - M2);
    float ss2 = e2;
#pragma unroll
    for (int o = 16; o; o >>= 1) ss2 += __shfl_xor_sync(0xFFFFFFFFu, ss2, o);
    if (lane == 0) sred[warp] = ss2;
    __syncthreads();
    float S2 = 0.f;
#pragma unroll
    for (int w = 0; w < 8; w++) S2 += sred[w];
    __syncthreads();
    attp[tid] = e2 / S2;
    __syncthreads();

    // weighted sums -> feat[256]
    if (tid < D2) {
        const float* bm = g_bodyM + (size_t)b * TBODY * D2 + tid;
        float s = 0.f;
#pragma unroll 8
        for (int t = 0; t < TBODY; t++) s += bm[(size_t)t * D2] * attb[t];
        feat[tid] = s;
    } else {
        int d = tid - D2;
        const float* pm = g_punM + (size_t)b * TPUN * D2 + d;
        float s = 0.f;
#pragma unroll 8
        for (int p = 0; p < TPUN; p++) s += pm[(size_t)p * D2] * attp[p];
        feat[D2 + d] = s;
    }
    __syncthreads();

    if (tid < 3) {
        float s = bd[tid];
        for (int k = 0; k < G4; k++) s += feat[k] * Wd[tid * G4 + k];
        outp[b * 3 + tid] = s;
    }
}

// ---------------- host launcher ----------------
extern "C" void kernel_launch(void* const* d_in, const int* in_sizes, int n_in,
                              void* d_out, int out_size)
{
    // Disambiguate input ordering: signature order has bWih_f (76800) at index 3,
    // dict-insertion order has w_u (384) at index 3.
    int base, iwu, iwd, ibd;
    if (in_sizes[3] == 76800) { base = 3; iwu = 15; iwd = 16; ibd = 17; }
    else                      { base = 6; iwu = 3;  iwd = 4;  ibd = 5;  }

    const int*   body_idx = (const int*)d_in[0];
    const int*   pun_idx  = (const int*)d_in[1];
    const float* emb      = (const float*)d_in[2];

    const float* Wih[4]; const float* Whh[4]; const float* bv[4];
    for (int s = 0; s < 4; s++) {
        Wih[s] = (const float*)d_in[base + 3 * s + 0];
        Whh[s] = (const float*)d_in[base + 3 * s + 1];
        bv[s]  = (const float*)d_in[base + 3 * s + 2];
    }
    const float* w_u = (const float*)d_in[iwu];
    const float* Wd  = (const float*)d_in[iwd];
    const float* bd  = (const float*)d_in[ibd];
    float* outp = (float*)d_out;

    zero_kernel<<<256, 256>>>();                              // covers 65536
    mark_kernel<<<(BATCH * (TBODY + TPUN)) / 256, 256>>>(body_idx, pun_idx);

    dim3 gg((VOCAB + BM - 1) / BM, 4, 2);
    gemm_tbl_kernel<<<gg, 256>>>(emb, Wih[0], Wih[1], Wih[2], Wih[3],
                                 bv[0], bv[1], bv[2], bv[3]);

    lstm_kernel<<<512, 512>>>(body_idx, pun_idx, Whh[0], Whh[1], Whh[2], Whh[3]);

    align_kernel<<<BATCH * 8, 256>>>(w_u);

    final_kernel<<<BATCH, 256>>>(Wd, bd, outp);
    (void)n_in; (void)out_size;
}

// round 12
// speedup vs baseline: 1.3822x; 1.3822x over previous
#include <cuda_runtime.h>
#include <cstdint>

#define VOCAB 50000
#define EMBD  300
#define HID   64
#define G4    256      // 4*H
#define D2    128      // 2*H
#define BATCH 128
#define TBODY 512
#define TPUN  256

// ---------------- scratch (static device arrays: allocation-free) ----------------
__device__ float    g_tbl[(size_t)4 * VOCAB * G4];          // 204.8 MB gate tables
__device__ float    g_bodyM[(size_t)BATCH * TBODY * D2];    // 33.5 MB
__device__ float    g_punM[(size_t)BATCH * TPUN * D2];      // 16.8 MB
__device__ unsigned g_rowmax[BATCH * TBODY];                // ordered-int encoded
__device__ unsigned g_colmax[BATCH * TPUN];                 // ordered-int encoded
__device__ float    g_a1[BATCH * TBODY];                    // w1 . bodyM row
__device__ float    g_a2[BATCH * TPUN];                     // w2 . punM row
__device__ int      g_flag[2][VOCAB];                       // 0 body, 1 pun
__device__ int      g_list[2][VOCAB];
__device__ int      g_cnt[2];

// ---------------- helpers ----------------
__device__ __forceinline__ unsigned enc_f(float f) {
    unsigned u = __float_as_uint(f);
    return (u & 0x80000000u) ? ~u : (u | 0x80000000u);
}
__device__ __forceinline__ float dec_f(unsigned u) {
    return __uint_as_float((u & 0x80000000u) ? (u ^ 0x80000000u) : ~u);
}
// packed fp32x2 FMA (sm_100+): 2 FMA per lane per issue
__device__ __forceinline__ unsigned long long ffma2(unsigned long long a,
                                                    unsigned long long b,
                                                    unsigned long long c) {
    unsigned long long d;
    asm("fma.rn.f32x2 %0, %1, %2, %3;" : "=l"(d) : "l"(a), "l"(b), "l"(c));
    return d;
}
__device__ __forceinline__ unsigned long long pk2(float x) {
    unsigned long long r;
    asm("mov.b64 %0, {%1, %1};" : "=l"(r) : "f"(x));
    return r;
}
__device__ __forceinline__ float2 up2(unsigned long long p) {
    float2 r;
    asm("mov.b64 {%0, %1}, %2;" : "=f"(r.x), "=f"(r.y) : "l"(p));
    return r;
}

// ---------------- kernel 0: zero flags/counters + encoded-max arrays ----------------
__global__ void zero_kernel() {
    int i = blockIdx.x * blockDim.x + threadIdx.x;   // grid covers 65536
    if (i < VOCAB) { g_flag[0][i] = 0; g_flag[1][i] = 0; }
    if (i == 0) { g_cnt[0] = 0; g_cnt[1] = 0; }
    if (i < BATCH * TBODY) g_rowmax[i] = 0u;
    if (i < BATCH * TPUN)  g_colmax[i] = 0u;
}

// ---------------- kernel 0b: mark used vocab ids, warp-aggregated compaction ------
__global__ void mark_kernel(const int* __restrict__ body_idx,
                            const int* __restrict__ pun_idx) {
    int i = blockIdx.x * blockDim.x + threadIdx.x;   // 98304 threads
    int which, v;
    if (i < BATCH * TBODY) { which = 0; v = body_idx[i]; }
    else                   { which = 1; v = pun_idx[i - BATCH * TBODY]; }
    // each warp is entirely one type (boundary 65536 is warp-aligned)
    bool isnew = (atomicExch(&g_flag[which][v], 1) == 0);
    unsigned mask = __ballot_sync(0xFFFFFFFFu, isnew);
    int n = __popc(mask);
    if (n) {
        int lane = threadIdx.x & 31;
        int leader = __ffs(mask) - 1;
        int base = 0;
        if (lane == leader) base = atomicAdd(&g_cnt[which], n);
        base = __shfl_sync(0xFFFFFFFFu, base, leader);
        if (isnew) g_list[which][base + __popc(mask & ((1u << lane) - 1))] = v;
    }
}

// ---------------- kernel 1: gate-table GEMM over USED vocab rows ------------------
#define BM 128
#define BN 128
#define BK 20
__global__ void __launch_bounds__(256, 2) gemm_tbl_kernel(
    const float* __restrict__ emb,
    const float* __restrict__ W0, const float* __restrict__ W1,
    const float* __restrict__ W2, const float* __restrict__ W3,
    const float* __restrict__ B0, const float* __restrict__ B1,
    const float* __restrict__ B2, const float* __restrict__ B3)
{
    int z = blockIdx.z;
    int cnt = g_cnt[z];
    int m0 = blockIdx.x * BM;
    if (m0 >= cnt) return;
    int y = blockIdx.y;
    int dir = y >> 1;
    int n0 = (y & 1) * 128;          // col offset within this direction's 256
    int seg = z * 2 + dir;
    const float* W    = (seg == 0) ? W0 : (seg == 1) ? W1 : (seg == 2) ? W2 : W3;
    const float* bias = (seg == 0) ? B0 : (seg == 1) ? B1 : (seg == 2) ? B2 : B3;
    float* out = g_tbl + (size_t)seg * VOCAB * G4;

    __shared__ __align__(16) unsigned long long As[2][BK][BM + 2];  // dup f32x2
    __shared__ __align__(16) float Bs[2][BK][BN + 4];
    __shared__ int ids[BM];

    int tid = threadIdx.x;
    int tx = tid & 15, ty = tid >> 4;

    if (tid < BM) ids[tid] = (m0 + tid < cnt) ? g_list[z][m0 + tid] : 0;
    __syncthreads();

    unsigned long long acc[8][4];
#pragma unroll
    for (int i = 0; i < 8; i++)
#pragma unroll
        for (int j = 0; j < 4; j++) acc[i][j] = 0ull;

    float ra[10], rb[10];
#pragma unroll
    for (int it = 0; it < 10; it++) {
        int l = tid + 256 * it;
        int r = l / BK, kk = l - r * BK;
        ra[it] = emb[(size_t)ids[r] * EMBD + kk];
        rb[it] = W[(size_t)(n0 + r) * EMBD + kk];
    }

    for (int ks = 0; ks < 15; ks++) {
        int buf = ks & 1;
#pragma unroll
        for (int it = 0; it < 10; it++) {
            int l = tid + 256 * it;
            int r = l / BK, kk = l - r * BK;
            As[buf][kk][r] = pk2(ra[it]);
            Bs[buf][kk][r] = rb[it];
        }
        __syncthreads();
        if (ks < 14) {
            int k0 = (ks + 1) * BK;
#pragma unroll
            for (int it = 0; it < 10; it++) {
                int l = tid + 256 * it;
                int r = l / BK, kk = l - r * BK;
                ra[it] = emb[(size_t)ids[r] * EMBD + k0 + kk];
                rb[it] = W[(size_t)(n0 + r) * EMBD + k0 + kk];
            }
        }
#pragma unroll
        for (int kk = 0; kk < BK; kk++) {
            ulonglong2 a01 = *(const ulonglong2*)&As[buf][kk][ty * 4];
            ulonglong2 a23 = *(const ulonglong2*)&As[buf][kk][ty * 4 + 2];
            ulonglong2 a45 = *(const ulonglong2*)&As[buf][kk][64 + ty * 4];
            ulonglong2 a67 = *(const ulonglong2*)&As[buf][kk][64 + ty * 4 + 2];
            ulonglong2 b0 = *(const ulonglong2*)&Bs[buf][kk][tx * 4];
            ulonglong2 b1 = *(const ulonglong2*)&Bs[buf][kk][64 + tx * 4];
            unsigned long long ap[8];
            ap[0] = a01.x; ap[1] = a01.y; ap[2] = a23.x; ap[3] = a23.y;
            ap[4] = a45.x; ap[5] = a45.y; ap[6] = a67.x; ap[7] = a67.y;
#pragma unroll
            for (int i = 0; i < 8; i++) {
                acc[i][0] = ffma2(ap[i], b0.x, acc[i][0]);
                acc[i][1] = ffma2(ap[i], b0.y, acc[i][1]);
                acc[i][2] = ffma2(ap[i], b1.x, acc[i][2]);
                acc[i][3] = ffma2(ap[i], b1.y, acc[i][3]);
            }
        }
    }

    float4 bs0 = *(const float4*)&bias[n0 + tx * 4];
    float4 bs1 = *(const float4*)&bias[n0 + 64 + tx * 4];
#pragma unroll
    for (int i = 0; i < 8; i++) {
        int r = ids[ty * 4 + (i & 3) + (i >> 2) * 64];
        float2 v0 = up2(acc[i][0]), v1 = up2(acc[i][1]);
        float2 v2 = up2(acc[i][2]), v3 = up2(acc[i][3]);
        float4 o0 = make_float4(v0.x + bs0.x, v0.y + bs0.y, v1.x + bs0.z, v1.y + bs0.w);
        float4 o1 = make_float4(v2.x + bs1.x, v2.y + bs1.y, v3.x + bs1.z, v3.y + bs1.w);
        *(float4*)&out[(size_t)r * G4 + n0 + tx * 4] = o0;
        *(float4*)&out[(size_t)r * G4 + n0 + 64 + tx * 4] = o1;
    }
}

// ---------------- kernel 2: LSTM, warp-local gate combine (R9 known-good) ---------
__global__ void __launch_bounds__(256, 2) lstm_kernel(
    const int* __restrict__ body_idx, const int* __restrict__ pun_idx,
    const float* __restrict__ Whh0, const float* __restrict__ Whh1,
    const float* __restrict__ Whh2, const float* __restrict__ Whh3)
{
    int blk = blockIdx.x;
    int seg = (blk >> 7) ^ 2;        // schedule puns (short) first
    int b   = blk & 127;
    bool isBody = (seg < 2);
    bool isFwd  = ((seg & 1) == 0);
    int T = isBody ? TBODY : TPUN;
    const int* idx = isBody ? (body_idx + b * TBODY) : (pun_idx + b * TPUN);
    const float* Whh = (seg == 0) ? Whh0 : (seg == 1) ? Whh1 : (seg == 2) ? Whh2 : Whh3;
    const float* tbl = g_tbl + (size_t)seg * VOCAB * G4;
    float* out = isBody ? (g_bodyM + (size_t)b * TBODY * D2)
                        : (g_punM  + (size_t)b * TPUN  * D2);
    int off = isFwd ? 0 : HID;

    __shared__ int idx_s[TBODY];
    __shared__ __align__(16) float hs[2][HID];
    __shared__ int len_s;

    int tid  = threadIdx.x;
    int lane = tid & 31;
    int warp = tid >> 5;
    int gc   = lane >> 3;                 // gate class: 0=i,1=f,2=g,3=o
    int u    = (warp << 3) | (lane & 7);  // hidden unit 0..63
    int r    = gc * HID + u;              // gate row 0..255

    if (tid == 0) len_s = 0;
    if (tid < HID) { hs[0][tid] = 0.f; hs[1][tid] = 0.f; }
    __syncthreads();

    int cnt = 0;
    for (int t = tid; t < T; t += 256) {
        int v = idx[t];
        idx_s[t] = v;
        cnt += (v != 0);
    }
#pragma unroll
    for (int o = 16; o; o >>= 1) cnt += __shfl_xor_sync(0xFFFFFFFFu, cnt, o);
    if (lane == 0) atomicAdd(&len_s, cnt);
    __syncthreads();
    int len = len_s;

    // Whh row r as 32 packed f32x2 pairs (row = 256 B, 8B-aligned)
    unsigned long long wp[32];
    {
        const unsigned long long* wr = (const unsigned long long*)(Whh + (size_t)r * HID);
#pragma unroll
        for (int j = 0; j < 32; j++) wp[j] = wr[j];
    }

    float c = 0.f;
    float x1 = 0.f, x2 = 0.f;
    if (len > 0) x1 = tbl[(size_t)idx_s[isFwd ? 0 : (len - 1)] * G4 + r];
    if (len > 1) x2 = tbl[(size_t)idx_s[isFwd ? 1 : (len - 2)] * G4 + r];

    for (int t = 0; t < len; t++) {
        float xs = x1;
        x1 = x2;
        if (t + 2 < len) {
            int p2 = isFwd ? (t + 2) : (len - 3 - t);
            x2 = tbl[(size_t)idx_s[p2] * G4 + r];
        }
        const ulonglong2* hp = (const ulonglong2*)hs[t & 1];
        unsigned long long a0 = 0ull, a1 = 0ull, a2 = 0ull, a3 = 0ull;
#pragma unroll
        for (int jj = 0; jj < 8; jj++) {
            ulonglong2 hA = hp[2 * jj];
            ulonglong2 hB = hp[2 * jj + 1];
            a0 = ffma2(wp[4 * jj + 0], hA.x, a0);
            a1 = ffma2(wp[4 * jj + 1], hA.y, a1);
            a2 = ffma2(wp[4 * jj + 2], hB.x, a2);
            a3 = ffma2(wp[4 * jj + 3], hB.y, a3);
        }
        float2 s0 = up2(a0), s1 = up2(a1), s2 = up2(a2), s3 = up2(a3);
        float pre = xs + ((s0.x + s0.y) + (s1.x + s1.y))
                       + ((s2.x + s2.y) + (s3.x + s3.y));
        float act = (gc == 2) ? tanhf(pre) : 1.f / (1.f + __expf(-pre));
        float fA = __shfl_sync(0xFFFFFFFFu, act, (lane + 8) & 31);
        float gA = __shfl_sync(0xFFFFFFFFu, act, (lane + 16) & 31);
        float oA = __shfl_sync(0xFFFFFFFFu, act, (lane + 24) & 31);
        if (gc == 0) {
            c = fA * c + act * gA;          // act = i-gate
            float h = oA * tanhf(c);
            hs[(t + 1) & 1][u] = h;
            int pos = isFwd ? t : (len - 1 - t);
            out[(size_t)pos * D2 + off + u] = h;
        }
        __syncthreads();
    }
    for (int l = tid; l < (T - len) * HID; l += 256) {
        int tpos = len + l / HID;
        int j = l - (l / HID) * HID;
        out[(size_t)tpos * D2 + off + j] = 0.f;
    }
}

// ---------------- kernel 2b: aux row-dots a1 = w1.body, a2 = w2.pun ---------------
// 128 blocks x 256 thr; warp per row; lane covers 4 consecutive d (float4).
__global__ void __launch_bounds__(256) aux_kernel(const float* __restrict__ w_u)
{
    int b = blockIdx.x;
    int tid = threadIdx.x;
    int lane = tid & 31, warp = tid >> 5;

    float4 w1v = *(const float4*)&w_u[lane * 4];
    float4 w2v = *(const float4*)&w_u[D2 + lane * 4];

    const float* bm = g_bodyM + (size_t)b * TBODY * D2;
    for (int r = warp; r < TBODY; r += 8) {
        float4 x = *(const float4*)&bm[(size_t)r * D2 + lane * 4];
        float s = x.x * w1v.x + x.y * w1v.y + x.z * w1v.z + x.w * w1v.w;
#pragma unroll
        for (int o = 16; o; o >>= 1) s += __shfl_xor_sync(0xFFFFFFFFu, s, o);
        if (lane == 0) g_a1[b * TBODY + r] = s;
    }
    const float* pm = g_punM + (size_t)b * TPUN * D2;
    for (int r = warp; r < TPUN; r += 8) {
        float4 x = *(const float4*)&pm[(size_t)r * D2 + lane * 4];
        float s = x.x * w2v.x + x.y * w2v.y + x.z * w2v.z + x.w * w2v.w;
#pragma unroll
        for (int o = 16; o; o >>= 1) s += __shfl_xor_sync(0xFFFFFFFFu, s, o);
        if (lane == 0) g_a2[b * TPUN + r] = s;
    }
}

// ---------------- kernel 3: alignment maxes, 64x64 tiles, 4 blocks/SM -------------
// grid = 128 batches * 8 t-chunks * 4 p-chunks = 4096 blocks, 256 thr.
// 4x4 micro (acc 8 ull), double-buffered smem, a1/a2 from global (aux_kernel).
#define ABK 16
__global__ void __launch_bounds__(256, 4) align_kernel(const float* __restrict__ w_u)
{
    int bx = blockIdx.x;
    int b  = bx >> 5;
    int tc = (bx >> 2) & 7;
    int pc = bx & 3;
    int t0 = tc * 64;
    int p0 = pc * 64;
    const float* bodyM = g_bodyM + (size_t)b * TBODY * D2;
    const float* punM  = g_punM  + (size_t)b * TPUN  * D2;

    __shared__ __align__(16) unsigned long long Bsu[2][ABK][66];  // [d][t] dup, w3 applied
    __shared__ __align__(16) float Ps[2][ABK][68];                // [d][p]
    __shared__ unsigned rms[64], cms[64];

    int tid = threadIdx.x;
    int tx = tid & 15, ty = tid >> 4;
    int q  = tid & 3;        // d-quad (4 d per quad)
    int rr = tid >> 2;       // row 0..63

    if (tid < 64) { rms[tid] = 0u; cms[tid] = 0u; }

    unsigned long long acc[4][2];
#pragma unroll
    for (int i = 0; i < 4; i++) { acc[i][0] = 0ull; acc[i][1] = 0ull; }

    // prefetch chunk 0 (one body row-quad + one pun row-quad per thread)
    float4 bv, pv;
    {
        float4 w3v = *(const float4*)&w_u[2 * D2 + 4 * q];
        float4 v = *(const float4*)&bodyM[(size_t)(t0 + rr) * D2 + 4 * q];
        bv = make_float4(v.x * w3v.x, v.y * w3v.y, v.z * w3v.z, v.w * w3v.w);
        pv = *(const float4*)&punM[(size_t)(p0 + rr) * D2 + 4 * q];
    }

    for (int kc = 0; kc < 8; kc++) {
        int buf = kc & 1;
        Bsu[buf][4 * q + 0][rr] = pk2(bv.x);
        Bsu[buf][4 * q + 1][rr] = pk2(bv.y);
        Bsu[buf][4 * q + 2][rr] = pk2(bv.z);
        Bsu[buf][4 * q + 3][rr] = pk2(bv.w);
        Ps[buf][4 * q + 0][rr] = pv.x;
        Ps[buf][4 * q + 1][rr] = pv.y;
        Ps[buf][4 * q + 2][rr] = pv.z;
        Ps[buf][4 * q + 3][rr] = pv.w;
        __syncthreads();
        if (kc < 7) {
            int d0 = (kc + 1) * ABK;
            float4 w3v = *(const float4*)&w_u[2 * D2 + d0 + 4 * q];
            float4 v = *(const float4*)&bodyM[(size_t)(t0 + rr) * D2 + d0 + 4 * q];
            bv = make_float4(v.x * w3v.x, v.y * w3v.y, v.z * w3v.z, v.w * w3v.w);
            pv = *(const float4*)&punM[(size_t)(p0 + rr) * D2 + d0 + 4 * q];
        }
#pragma unroll
        for (int d = 0; d < ABK; d++) {
            ulonglong2 a01 = *(const ulonglong2*)&Bsu[buf][d][ty * 4];
            ulonglong2 a23 = *(const ulonglong2*)&Bsu[buf][d][ty * 4 + 2];
            ulonglong2 bb  = *(const ulonglong2*)&Ps[buf][d][tx * 4];
            acc[0][0] = ffma2(a01.x, bb.x, acc[0][0]);
            acc[0][1] = ffma2(a01.x, bb.y, acc[0][1]);
            acc[1][0] = ffma2(a01.y, bb.x, acc[1][0]);
            acc[1][1] = ffma2(a01.y, bb.y, acc[1][1]);
            acc[2][0] = ffma2(a23.x, bb.x, acc[2][0]);
            acc[2][1] = ffma2(a23.x, bb.y, acc[2][1]);
            acc[3][0] = ffma2(a23.y, bb.x, acc[3][0]);
            acc[3][1] = ffma2(a23.y, bb.y, acc[3][1]);
        }
    }

    // epilogue: add a1/a2, fused row/col max
    float a2v[4];
#pragma unroll
    for (int j = 0; j < 4; j++) a2v[j] = g_a2[b * TPUN + p0 + tx * 4 + j];

    float cmax[4];
#pragma unroll
    for (int j = 0; j < 4; j++) cmax[j] = -1e30f;
#pragma unroll
    for (int i = 0; i < 4; i++) {
        float a1v = g_a1[b * TBODY + t0 + ty * 4 + i];
        float rmax = -1e30f;
#pragma unroll
        for (int j2 = 0; j2 < 2; j2++) {
            float2 v = up2(acc[i][j2]);
            float v0 = v.x + a1v + a2v[j2 * 2];
            float v1 = v.y + a1v + a2v[j2 * 2 + 1];
            rmax = fmaxf(rmax, fmaxf(v0, v1));
            cmax[j2 * 2]     = fmaxf(cmax[j2 * 2], v0);
            cmax[j2 * 2 + 1] = fmaxf(cmax[j2 * 2 + 1], v1);
        }
        atomicMax(&rms[ty * 4 + i], enc_f(rmax));
    }
#pragma unroll
    for (int j = 0; j < 4; j++)
        atomicMax(&cms[tx * 4 + j], enc_f(cmax[j]));
    __syncthreads();

    if (tid < 64) {
        atomicMax(&g_rowmax[b * TBODY + t0 + tid], rms[tid]);
        atomicMax(&g_colmax[b * TPUN + p0 + tid], cms[tid]);
    }
}

// ---------------- kernel 4: softmaxes + weighted sums + final linear (512 thr) ----
__global__ void __launch_bounds__(512) final_kernel(
    const float* __restrict__ Wd, const float* __restrict__ bd,
    float* __restrict__ outp)
{
    int b = blockIdx.x;
    int tid = threadIdx.x;
    int lane = tid & 31, warp = tid >> 5;   // 16 warps

    __shared__ float attb[TBODY];
    __shared__ float attp[TPUN];
    __shared__ float part[512];
    __shared__ float feat[G4];
    __shared__ float sred[16];

    // softmax over rowmax[512]
    float v = dec_f(g_rowmax[b * TBODY + tid]);
    float m = v;
#pragma unroll
    for (int o = 16; o; o >>= 1) m = fmaxf(m, __shfl_xor_sync(0xFFFFFFFFu, m, o));
    if (lane == 0) sred[warp] = m;
    __syncthreads();
    float M = sred[0];
#pragma unroll
    for (int w = 1; w < 16; w++) M = fmaxf(M, sred[w]);
    __syncthreads();
    float e = __expf(v - M);
    float ss = e;
#pragma unroll
    for (int o = 16; o; o >>= 1) ss += __shfl_xor_sync(0xFFFFFFFFu, ss, o);
    if (lane == 0) sred[warp] = ss;
    __syncthreads();
    float S = 0.f;
#pragma unroll
    for (int w = 0; w < 16; w++) S += sred[w];
    __syncthreads();
    attb[tid] = e / S;

    // softmax over colmax[256]
    float u = (tid < TPUN) ? dec_f(g_colmax[b * TPUN + tid]) : -1e30f;
    float m2 = u;
#pragma unroll
    for (int o = 16; o; o >>= 1) m2 = fmaxf(m2, __shfl_xor_sync(0xFFFFFFFFu, m2, o));
    if (lane == 0) sred[warp] = m2;
    __syncthreads();
    float M2 = sred[0];
#pragma unroll
    for (int w = 1; w < 16; w++) M2 = fmaxf(M2, sred[w]);
    __syncthreads();
    float e2 = (tid < TPUN) ? __expf(u - M2) : 0.f;
    float ss2 = e2;
#pragma unroll
    for (int o = 16; o; o >>= 1) ss2 += __shfl_xor_sync(0xFFFFFFFFu, ss2, o);
    if (lane == 0) sred[warp] = ss2;
    __syncthreads();
    float S2 = 0.f;
#pragma unroll
    for (int w = 0; w < 16; w++) S2 += sred[w];
    if (tid < TPUN) attp[tid] = e2 / S2;
    __syncthreads();

    // weighted sums, split in 2 row-halves per column
    int col = tid & 255, half = tid >> 8;
    float s = 0.f;
    if (col < D2) {
        const float* bm = g_bodyM + (size_t)b * TBODY * D2 + col;
        int tbeg = half * 256, tend = tbeg + 256;
#pragma unroll 8
        for (int t = tbeg; t < tend; t++) s += bm[(size_t)t * D2] * attb[t];
    } else {
        int d = col - D2;
        const float* pm = g_punM + (size_t)b * TPUN * D2 + d;
        int pbeg = half * 128, pend = pbeg + 128;
#pragma unroll 8
        for (int p = pbeg; p < pend; p++) s += pm[(size_t)p * D2] * attp[p];
    }
    part[tid] = s;
    __syncthreads();
    if (tid < G4) feat[tid] = part[tid] + part[tid + 256];
    __syncthreads();

    if (tid < 3) {
        float sum = bd[tid];
        for (int k = 0; k < G4; k++) sum += feat[k] * Wd[tid * G4 + k];
        outp[b * 3 + tid] = sum;
    }
}

// ---------------- host launcher ----------------
extern "C" void kernel_launch(void* const* d_in, const int* in_sizes, int n_in,
                              void* d_out, int out_size)
{
    // Disambiguate input ordering: signature order has bWih_f (76800) at index 3,
    // dict-insertion order has w_u (384) at index 3.
    int base, iwu, iwd, ibd;
    if (in_sizes[3] == 76800) { base = 3; iwu = 15; iwd = 16; ibd = 17; }
    else                      { base = 6; iwu = 3;  iwd = 4;  ibd = 5;  }

    const int*   body_idx = (const int*)d_in[0];
    const int*   pun_idx  = (const int*)d_in[1];
    const float* emb      = (const float*)d_in[2];

    const float* Wih[4]; const float* Whh[4]; const float* bv[4];
    for (int s = 0; s < 4; s++) {
        Wih[s] = (const float*)d_in[base + 3 * s + 0];
        Whh[s] = (const float*)d_in[base + 3 * s + 1];
        bv[s]  = (const float*)d_in[base + 3 * s + 2];
    }
    const float* w_u = (const float*)d_in[iwu];
    const float* Wd  = (const float*)d_in[iwd];
    const float* bd  = (const float*)d_in[ibd];
    float* outp = (float*)d_out;

    zero_kernel<<<256, 256>>>();                              // covers 65536
    mark_kernel<<<(BATCH * (TBODY + TPUN)) / 256, 256>>>(body_idx, pun_idx);

    dim3 gg((VOCAB + BM - 1) / BM, 4, 2);
    gemm_tbl_kernel<<<gg, 256>>>(emb, Wih[0], Wih[1], Wih[2], Wih[3],
                                 bv[0], bv[1], bv[2], bv[3]);

    lstm_kernel<<<512, 256>>>(body_idx, pun_idx, Whh[0], Whh[1], Whh[2], Whh[3]);

    aux_kernel<<<BATCH, 256>>>(w_u);

    align_kernel<<<BATCH * 32, 256>>>(w_u);

    final_kernel<<<BATCH, 512>>>(Wd, bd, outp);
    (void)n_in; (void)out_size;
}

// round 13
// speedup vs baseline: 1.4197x; 1.0271x over previous
#include <cuda_runtime.h>
#include <cstdint>

#define VOCAB 50000
#define EMBD  300
#define HID   64
#define G4    256      // 4*H
#define D2    128      // 2*H
#define BATCH 128
#define TBODY 512
#define TPUN  256

// ---------------- scratch (static device arrays: allocation-free) ----------------
__device__ float    g_tbl[(size_t)4 * VOCAB * G4];          // 204.8 MB gate tables
__device__ float    g_bodyM[(size_t)BATCH * TBODY * D2];    // 33.5 MB
__device__ float    g_punM[(size_t)BATCH * TPUN * D2];      // 16.8 MB
__device__ unsigned g_rowmax[BATCH * TBODY];                // ordered-int encoded
__device__ unsigned g_colmax[BATCH * TPUN];                 // ordered-int encoded
__device__ float    g_a1[BATCH * TBODY];                    // w1 . bodyM row
__device__ float    g_a2[BATCH * TPUN];                     // w2 . punM row
__device__ int      g_flag[2][VOCAB];                       // 0 body, 1 pun
__device__ int      g_list[2][VOCAB];
__device__ int      g_cnt[2];

// ---------------- helpers ----------------
__device__ __forceinline__ unsigned enc_f(float f) {
    unsigned u = __float_as_uint(f);
    return (u & 0x80000000u) ? ~u : (u | 0x80000000u);
}
__device__ __forceinline__ float dec_f(unsigned u) {
    return __uint_as_float((u & 0x80000000u) ? (u ^ 0x80000000u) : ~u);
}
// packed fp32x2 FMA (sm_100+): 2 FMA per lane per issue
__device__ __forceinline__ unsigned long long ffma2(unsigned long long a,
                                                    unsigned long long b,
                                                    unsigned long long c) {
    unsigned long long d;
    asm("fma.rn.f32x2 %0, %1, %2, %3;" : "=l"(d) : "l"(a), "l"(b), "l"(c));
    return d;
}
__device__ __forceinline__ unsigned long long pk2(float x) {
    unsigned long long r;
    asm("mov.b64 %0, {%1, %1};" : "=l"(r) : "f"(x));
    return r;
}
__device__ __forceinline__ float2 up2(unsigned long long p) {
    float2 r;
    asm("mov.b64 {%0, %1}, %2;" : "=f"(r.x), "=f"(r.y) : "l"(p));
    return r;
}
// fast activations via MUFU.EX2 path; rel err ~1e-6 (<< 1e-3 budget)
__device__ __forceinline__ float fast_sigmoid(float x) {
    return __fdividef(1.f, 1.f + __expf(-x));
}
__device__ __forceinline__ float fast_tanh(float x) {
    return 1.f - __fdividef(2.f, __expf(2.f * x) + 1.f);
}

// ---------------- kernel 0: zero flags/counters + encoded-max arrays ----------------
__global__ void zero_kernel() {
    int i = blockIdx.x * blockDim.x + threadIdx.x;   // grid covers 65536
    if (i < VOCAB) { g_flag[0][i] = 0; g_flag[1][i] = 0; }
    if (i == 0) { g_cnt[0] = 0; g_cnt[1] = 0; }
    if (i < BATCH * TBODY) g_rowmax[i] = 0u;
    if (i < BATCH * TPUN)  g_colmax[i] = 0u;
}

// ---------------- kernel 0b: mark used vocab ids, warp-aggregated compaction ------
__global__ void mark_kernel(const int* __restrict__ body_idx,
                            const int* __restrict__ pun_idx) {
    int i = blockIdx.x * blockDim.x + threadIdx.x;   // 98304 threads
    int which, v;
    if (i < BATCH * TBODY) { which = 0; v = body_idx[i]; }
    else                   { which = 1; v = pun_idx[i - BATCH * TBODY]; }
    // each warp is entirely one type (boundary 65536 is warp-aligned)
    bool isnew = (atomicExch(&g_flag[which][v], 1) == 0);
    unsigned mask = __ballot_sync(0xFFFFFFFFu, isnew);
    int n = __popc(mask);
    if (n) {
        int lane = threadIdx.x & 31;
        int leader = __ffs(mask) - 1;
        int base = 0;
        if (lane == leader) base = atomicAdd(&g_cnt[which], n);
        base = __shfl_sync(0xFFFFFFFFu, base, leader);
        if (isnew) g_list[which][base + __popc(mask & ((1u << lane) - 1))] = v;
    }
}

// ---------------- kernel 1: gate-table GEMM over USED vocab rows ------------------
#define BM 128
#define BN 128
#define BK 20
__global__ void __launch_bounds__(256, 2) gemm_tbl_kernel(
    const float* __restrict__ emb,
    const float* __restrict__ W0, const float* __restrict__ W1,
    const float* __restrict__ W2, const float* __restrict__ W3,
    const float* __restrict__ B0, const float* __restrict__ B1,
    const float* __restrict__ B2, const float* __restrict__ B3)
{
    int z = blockIdx.z;
    int cnt = g_cnt[z];
    int m0 = blockIdx.x * BM;
    if (m0 >= cnt) return;
    int y = blockIdx.y;
    int dir = y >> 1;
    int n0 = (y & 1) * 128;          // col offset within this direction's 256
    int seg = z * 2 + dir;
    const float* W    = (seg == 0) ? W0 : (seg == 1) ? W1 : (seg == 2) ? W2 : W3;
    const float* bias = (seg == 0) ? B0 : (seg == 1) ? B1 : (seg == 2) ? B2 : B3;
    float* out = g_tbl + (size_t)seg * VOCAB * G4;

    __shared__ __align__(16) unsigned long long As[2][BK][BM + 2];  // dup f32x2
    __shared__ __align__(16) float Bs[2][BK][BN + 4];
    __shared__ int ids[BM];

    int tid = threadIdx.x;
    int tx = tid & 15, ty = tid >> 4;

    if (tid < BM) ids[tid] = (m0 + tid < cnt) ? g_list[z][m0 + tid] : 0;
    __syncthreads();

    unsigned long long acc[8][4];
#pragma unroll
    for (int i = 0; i < 8; i++)
#pragma unroll
        for (int j = 0; j < 4; j++) acc[i][j] = 0ull;

    float ra[10], rb[10];
#pragma unroll
    for (int it = 0; it < 10; it++) {
        int l = tid + 256 * it;
        int r = l / BK, kk = l - r * BK;
        ra[it] = emb[(size_t)ids[r] * EMBD + kk];
        rb[it] = W[(size_t)(n0 + r) * EMBD + kk];
    }

    for (int ks = 0; ks < 15; ks++) {
        int buf = ks & 1;
#pragma unroll
        for (int it = 0; it < 10; it++) {
            int l = tid + 256 * it;
            int r = l / BK, kk = l - r * BK;
            As[buf][kk][r] = pk2(ra[it]);
            Bs[buf][kk][r] = rb[it];
        }
        __syncthreads();
        if (ks < 14) {
            int k0 = (ks + 1) * BK;
#pragma unroll
            for (int it = 0; it < 10; it++) {
                int l = tid + 256 * it;
                int r = l / BK, kk = l - r * BK;
                ra[it] = emb[(size_t)ids[r] * EMBD + k0 + kk];
                rb[it] = W[(size_t)(n0 + r) * EMBD + k0 + kk];
            }
        }
#pragma unroll
        for (int kk = 0; kk < BK; kk++) {
            ulonglong2 a01 = *(const ulonglong2*)&As[buf][kk][ty * 4];
            ulonglong2 a23 = *(const ulonglong2*)&As[buf][kk][ty * 4 + 2];
            ulonglong2 a45 = *(const ulonglong2*)&As[buf][kk][64 + ty * 4];
            ulonglong2 a67 = *(const ulonglong2*)&As[buf][kk][64 + ty * 4 + 2];
            ulonglong2 b0 = *(const ulonglong2*)&Bs[buf][kk][tx * 4];
            ulonglong2 b1 = *(const ulonglong2*)&Bs[buf][kk][64 + tx * 4];
            unsigned long long ap[8];
            ap[0] = a01.x; ap[1] = a01.y; ap[2] = a23.x; ap[3] = a23.y;
            ap[4] = a45.x; ap[5] = a45.y; ap[6] = a67.x; ap[7] = a67.y;
#pragma unroll
            for (int i = 0; i < 8; i++) {
                acc[i][0] = ffma2(ap[i], b0.x, acc[i][0]);
                acc[i][1] = ffma2(ap[i], b0.y, acc[i][1]);
                acc[i][2] = ffma2(ap[i], b1.x, acc[i][2]);
                acc[i][3] = ffma2(ap[i], b1.y, acc[i][3]);
            }
        }
    }

    float4 bs0 = *(const float4*)&bias[n0 + tx * 4];
    float4 bs1 = *(const float4*)&bias[n0 + 64 + tx * 4];
#pragma unroll
    for (int i = 0; i < 8; i++) {
        int r = ids[ty * 4 + (i & 3) + (i >> 2) * 64];
        float2 v0 = up2(acc[i][0]), v1 = up2(acc[i][1]);
        float2 v2 = up2(acc[i][2]), v3 = up2(acc[i][3]);
        float4 o0 = make_float4(v0.x + bs0.x, v0.y + bs0.y, v1.x + bs0.z, v1.y + bs0.w);
        float4 o1 = make_float4(v2.x + bs1.x, v2.y + bs1.y, v3.x + bs1.z, v3.y + bs1.w);
        *(float4*)&out[(size_t)r * G4 + n0 + tx * 4] = o0;
        *(float4*)&out[(size_t)r * G4 + n0 + 64 + tx * 4] = o1;
    }
}

// ---------------- kernel 2: LSTM (R9 structure + fast activations) ----------------
__global__ void __launch_bounds__(256, 2) lstm_kernel(
    const int* __restrict__ body_idx, const int* __restrict__ pun_idx,
    const float* __restrict__ Whh0, const float* __restrict__ Whh1,
    const float* __restrict__ Whh2, const float* __restrict__ Whh3)
{
    int blk = blockIdx.x;
    int seg = (blk >> 7) ^ 2;        // schedule puns (short) first
    int b   = blk & 127;
    bool isBody = (seg < 2);
    bool isFwd  = ((seg & 1) == 0);
    int T = isBody ? TBODY : TPUN;
    const int* idx = isBody ? (body_idx + b * TBODY) : (pun_idx + b * TPUN);
    const float* Whh = (seg == 0) ? Whh0 : (seg == 1) ? Whh1 : (seg == 2) ? Whh2 : Whh3;
    const float* tbl = g_tbl + (size_t)seg * VOCAB * G4;
    float* out = isBody ? (g_bodyM + (size_t)b * TBODY * D2)
                        : (g_punM  + (size_t)b * TPUN  * D2);
    int off = isFwd ? 0 : HID;

    __shared__ int idx_s[TBODY];
    __shared__ __align__(16) float hs[2][HID];
    __shared__ int len_s;

    int tid  = threadIdx.x;
    int lane = tid & 31;
    int warp = tid >> 5;
    int gc   = lane >> 3;                 // gate class: 0=i,1=f,2=g,3=o
    int u    = (warp << 3) | (lane & 7);  // hidden unit 0..63
    int r    = gc * HID + u;              // gate row 0..255

    if (tid == 0) len_s = 0;
    if (tid < HID) { hs[0][tid] = 0.f; hs[1][tid] = 0.f; }
    __syncthreads();

    int cnt = 0;
    for (int t = tid; t < T; t += 256) {
        int v = idx[t];
        idx_s[t] = v;
        cnt += (v != 0);
    }
#pragma unroll
    for (int o = 16; o; o >>= 1) cnt += __shfl_xor_sync(0xFFFFFFFFu, cnt, o);
    if (lane == 0) atomicAdd(&len_s, cnt);
    __syncthreads();
    int len = len_s;

    // Whh row r as 32 packed f32x2 pairs (row = 256 B, 8B-aligned)
    unsigned long long wp[32];
    {
        const unsigned long long* wr = (const unsigned long long*)(Whh + (size_t)r * HID);
#pragma unroll
        for (int j = 0; j < 32; j++) wp[j] = wr[j];
    }

    float c = 0.f;
    float x1 = 0.f, x2 = 0.f;
    if (len > 0) x1 = tbl[(size_t)idx_s[isFwd ? 0 : (len - 1)] * G4 + r];
    if (len > 1) x2 = tbl[(size_t)idx_s[isFwd ? 1 : (len - 2)] * G4 + r];

    for (int t = 0; t < len; t++) {
        float xs = x1;
        x1 = x2;
        if (t + 2 < len) {
            int p2 = isFwd ? (t + 2) : (len - 3 - t);
            x2 = tbl[(size_t)idx_s[p2] * G4 + r];
        }
        const ulonglong2* hp = (const ulonglong2*)hs[t & 1];
        unsigned long long a0 = 0ull, a1 = 0ull, a2 = 0ull, a3 = 0ull;
#pragma unroll
        for (int jj = 0; jj < 8; jj++) {
            ulonglong2 hA = hp[2 * jj];
            ulonglong2 hB = hp[2 * jj + 1];
            a0 = ffma2(wp[4 * jj + 0], hA.x, a0);
            a1 = ffma2(wp[4 * jj + 1], hA.y, a1);
            a2 = ffma2(wp[4 * jj + 2], hB.x, a2);
            a3 = ffma2(wp[4 * jj + 3], hB.y, a3);
        }
        float2 s0 = up2(a0), s1 = up2(a1), s2 = up2(a2), s3 = up2(a3);
        float pre = xs + ((s0.x + s0.y) + (s1.x + s1.y))
                       + ((s2.x + s2.y) + (s3.x + s3.y));
        float act = (gc == 2) ? fast_tanh(pre) : fast_sigmoid(pre);
        float fA = __shfl_sync(0xFFFFFFFFu, act, (lane + 8) & 31);
        float gA = __shfl_sync(0xFFFFFFFFu, act, (lane + 16) & 31);
        float oA = __shfl_sync(0xFFFFFFFFu, act, (lane + 24) & 31);
        if (gc == 0) {
            c = fA * c + act * gA;          // act = i-gate
            float h = oA * fast_tanh(c);
            hs[(t + 1) & 1][u] = h;
            int pos = isFwd ? t : (len - 1 - t);
            out[(size_t)pos * D2 + off + u] = h;
        }
        __syncthreads();
    }
    for (int l = tid; l < (T - len) * HID; l += 256) {
        int tpos = len + l / HID;
        int j = l - (l / HID) * HID;
        out[(size_t)tpos * D2 + off + j] = 0.f;
    }
}

// ---------------- kernel 2b: aux row-dots a1 = w1.body, a2 = w2.pun ---------------
// 128 blocks x 256 thr; warp per row; lane covers 4 consecutive d (float4).
__global__ void __launch_bounds__(256) aux_kernel(const float* __restrict__ w_u)
{
    int b = blockIdx.x;
    int tid = threadIdx.x;
    int lane = tid & 31, warp = tid >> 5;

    float4 w1v = *(const float4*)&w_u[lane * 4];
    float4 w2v = *(const float4*)&w_u[D2 + lane * 4];

    const float* bm = g_bodyM + (size_t)b * TBODY * D2;
    for (int r = warp; r < TBODY; r += 8) {
        float4 x = *(const float4*)&bm[(size_t)r * D2 + lane * 4];
        float s = x.x * w1v.x + x.y * w1v.y + x.z * w1v.z + x.w * w1v.w;
#pragma unroll
        for (int o = 16; o; o >>= 1) s += __shfl_xor_sync(0xFFFFFFFFu, s, o);
        if (lane == 0) g_a1[b * TBODY + r] = s;
    }
    const float* pm = g_punM + (size_t)b * TPUN * D2;
    for (int r = warp; r < TPUN; r += 8) {
        float4 x = *(const float4*)&pm[(size_t)r * D2 + lane * 4];
        float s = x.x * w2v.x + x.y * w2v.y + x.z * w2v.z + x.w * w2v.w;
#pragma unroll
        for (int o = 16; o; o >>= 1) s += __shfl_xor_sync(0xFFFFFFFFu, s, o);
        if (lane == 0) g_a2[b * TPUN + r] = s;
    }
}

// ---------------- kernel 3: alignment maxes, 64x64 tiles, 4 blocks/SM -------------
#define ABK 16
__global__ void __launch_bounds__(256, 4) align_kernel(const float* __restrict__ w_u)
{
    int bx = blockIdx.x;
    int b  = bx >> 5;
    int tc = (bx >> 2) & 7;
    int pc = bx & 3;
    int t0 = tc * 64;
    int p0 = pc * 64;
    const float* bodyM = g_bodyM + (size_t)b * TBODY * D2;
    const float* punM  = g_punM  + (size_t)b * TPUN  * D2;

    __shared__ __align__(16) unsigned long long Bsu[2][ABK][66];  // [d][t] dup, w3 applied
    __shared__ __align__(16) float Ps[2][ABK][68];                // [d][p]
    __shared__ unsigned rms[64], cms[64];

    int tid = threadIdx.x;
    int tx = tid & 15, ty = tid >> 4;
    int q  = tid & 3;        // d-quad (4 d per quad)
    int rr = tid >> 2;       // row 0..63

    if (tid < 64) { rms[tid] = 0u; cms[tid] = 0u; }

    unsigned long long acc[4][2];
#pragma unroll
    for (int i = 0; i < 4; i++) { acc[i][0] = 0ull; acc[i][1] = 0ull; }

    // prefetch chunk 0 (one body row-quad + one pun row-quad per thread)
    float4 bv, pv;
    {
        float4 w3v = *(const float4*)&w_u[2 * D2 + 4 * q];
        float4 v = *(const float4*)&bodyM[(size_t)(t0 + rr) * D2 + 4 * q];
        bv = make_float4(v.x * w3v.x, v.y * w3v.y, v.z * w3v.z, v.w * w3v.w);
        pv = *(const float4*)&punM[(size_t)(p0 + rr) * D2 + 4 * q];
    }

    for (int kc = 0; kc < 8; kc++) {
        int buf = kc & 1;
        Bsu[buf][4 * q + 0][rr] = pk2(bv.x);
        Bsu[buf][4 * q + 1][rr] = pk2(bv.y);
        Bsu[buf][4 * q + 2][rr] = pk2(bv.z);
        Bsu[buf][4 * q + 3][rr] = pk2(bv.w);
        Ps[buf][4 * q + 0][rr] = pv.x;
        Ps[buf][4 * q + 1][rr] = pv.y;
        Ps[buf][4 * q + 2][rr] = pv.z;
        Ps[buf][4 * q + 3][rr] = pv.w;
        __syncthreads();
        if (kc < 7) {
            int d0 = (kc + 1) * ABK;
            float4 w3v = *(const float4*)&w_u[2 * D2 + d0 + 4 * q];
            float4 v = *(const float4*)&bodyM[(size_t)(t0 + rr) * D2 + d0 + 4 * q];
            bv = make_float4(v.x * w3v.x, v.y * w3v.y, v.z * w3v.z, v.w * w3v.w);
            pv = *(const float4*)&punM[(size_t)(p0 + rr) * D2 + d0 + 4 * q];
        }
#pragma unroll
        for (int d = 0; d < ABK; d++) {
            ulonglong2 a01 = *(const ulonglong2*)&Bsu[buf][d][ty * 4];
            ulonglong2 a23 = *(const ulonglong2*)&Bsu[buf][d][ty * 4 + 2];
            ulonglong2 bb  = *(const ulonglong2*)&Ps[buf][d][tx * 4];
            acc[0][0] = ffma2(a01.x, bb.x, acc[0][0]);
            acc[0][1] = ffma2(a01.x, bb.y, acc[0][1]);
            acc[1][0] = ffma2(a01.y, bb.x, acc[1][0]);
            acc[1][1] = ffma2(a01.y, bb.y, acc[1][1]);
            acc[2][0] = ffma2(a23.x, bb.x, acc[2][0]);
            acc[2][1] = ffma2(a23.x, bb.y, acc[2][1]);
            acc[3][0] = ffma2(a23.y, bb.x, acc[3][0]);
            acc[3][1] = ffma2(a23.y, bb.y, acc[3][1]);
        }
    }

    // epilogue: add a1/a2, fused row/col max
    float a2v[4];
#pragma unroll
    for (int j = 0; j < 4; j++) a2v[j] = g_a2[b * TPUN + p0 + tx * 4 + j];

    float cmax[4];
#pragma unroll
    for (int j = 0; j < 4; j++) cmax[j] = -1e30f;
#pragma unroll
    for (int i = 0; i < 4; i++) {
        float a1v = g_a1[b * TBODY + t0 + ty * 4 + i];
        float rmax = -1e30f;
#pragma unroll
        for (int j2 = 0; j2 < 2; j2++) {
            float2 v = up2(acc[i][j2]);
            float v0 = v.x + a1v + a2v[j2 * 2];
            float v1 = v.y + a1v + a2v[j2 * 2 + 1];
            rmax = fmaxf(rmax, fmaxf(v0, v1));
            cmax[j2 * 2]     = fmaxf(cmax[j2 * 2], v0);
            cmax[j2 * 2 + 1] = fmaxf(cmax[j2 * 2 + 1], v1);
        }
        atomicMax(&rms[ty * 4 + i], enc_f(rmax));
    }
#pragma unroll
    for (int j = 0; j < 4; j++)
        atomicMax(&cms[tx * 4 + j], enc_f(cmax[j]));
    __syncthreads();

    if (tid < 64) {
        atomicMax(&g_rowmax[b * TBODY + t0 + tid], rms[tid]);
        atomicMax(&g_colmax[b * TPUN + p0 + tid], cms[tid]);
    }
}

// ---------------- kernel 4: softmaxes + weighted sums + final linear (512 thr) ----
__global__ void __launch_bounds__(512) final_kernel(
    const float* __restrict__ Wd, const float* __restrict__ bd,
    float* __restrict__ outp)
{
    int b = blockIdx.x;
    int tid = threadIdx.x;
    int lane = tid & 31, warp = tid >> 5;   // 16 warps

    __shared__ float attb[TBODY];
    __shared__ float attp[TPUN];
    __shared__ float part[512];
    __shared__ float feat[G4];
    __shared__ float sred[16];

    // softmax over rowmax[512]
    float v = dec_f(g_rowmax[b * TBODY + tid]);
    float m = v;
#pragma unroll
    for (int o = 16; o; o >>= 1) m = fmaxf(m, __shfl_xor_sync(0xFFFFFFFFu, m, o));
    if (lane == 0) sred[warp] = m;
    __syncthreads();
    float M = sred[0];
#pragma unroll
    for (int w = 1; w < 16; w++) M = fmaxf(M, sred[w]);
    __syncthreads();
    float e = __expf(v - M);
    float ss = e;
#pragma unroll
    for (int o = 16; o; o >>= 1) ss += __shfl_xor_sync(0xFFFFFFFFu, ss, o);
    if (lane == 0) sred[warp] = ss;
    __syncthreads();
    float S = 0.f;
#pragma unroll
    for (int w = 0; w < 16; w++) S += sred[w];
    __syncthreads();
    attb[tid] = e / S;

    // softmax over colmax[256]
    float u = (tid < TPUN) ? dec_f(g_colmax[b * TPUN + tid]) : -1e30f;
    float m2 = u;
#pragma unroll
    for (int o = 16; o; o >>= 1) m2 = fmaxf(m2, __shfl_xor_sync(0xFFFFFFFFu, m2, o));
    if (lane == 0) sred[warp] = m2;
    __syncthreads();
    float M2 = sred[0];
#pragma unroll
    for (int w = 1; w < 16; w++) M2 = fmaxf(M2, sred[w]);
    __syncthreads();
    float e2 = (tid < TPUN) ? __expf(u - M2) : 0.f;
    float ss2 = e2;
#pragma unroll
    for (int o = 16; o; o >>= 1) ss2 += __shfl_xor_sync(0xFFFFFFFFu, ss2, o);
    if (lane == 0) sred[warp] = ss2;
    __syncthreads();
    float S2 = 0.f;
#pragma unroll
    for (int w = 0; w < 16; w++) S2 += sred[w];
    if (tid < TPUN) attp[tid] = e2 / S2;
    __syncthreads();

    // weighted sums, split in 2 row-halves per column
    int col = tid & 255, half = tid >> 8;
    float s = 0.f;
    if (col < D2) {
        const float* bm = g_bodyM + (size_t)b * TBODY * D2 + col;
        int tbeg = half * 256, tend = tbeg + 256;
#pragma unroll 8
        for (int t = tbeg; t < tend; t++) s += bm[(size_t)t * D2] * attb[t];
    } else {
        int d = col - D2;
        const float* pm = g_punM + (size_t)b * TPUN * D2 + d;
        int pbeg = half * 128, pend = pbeg + 128;
#pragma unroll 8
        for (int p = pbeg; p < pend; p++) s += pm[(size_t)p * D2] * attp[p];
    }
    part[tid] = s;
    __syncthreads();
    if (tid < G4) feat[tid] = part[tid] + part[tid + 256];
    __syncthreads();

    if (tid < 3) {
        float sum = bd[tid];
        for (int k = 0; k < G4; k++) sum += feat[k] * Wd[tid * G4 + k];
        outp[b * 3 + tid] = sum;
    }
}

// ---------------- host launcher ----------------
extern "C" void kernel_launch(void* const* d_in, const int* in_sizes, int n_in,
                              void* d_out, int out_size)
{
    // Disambiguate input ordering: signature order has bWih_f (76800) at index 3,
    // dict-insertion order has w_u (384) at index 3.
    int base, iwu, iwd, ibd;
    if (in_sizes[3] == 76800) { base = 3; iwu = 15; iwd = 16; ibd = 17; }
    else                      { base = 6; iwu = 3;  iwd = 4;  ibd = 5;  }

    const int*   body_idx = (const int*)d_in[0];
    const int*   pun_idx  = (const int*)d_in[1];
    const float* emb      = (const float*)d_in[2];

    const float* Wih[4]; const float* Whh[4]; const float* bv[4];
    for (int s = 0; s < 4; s++) {
        Wih[s] = (const float*)d_in[base + 3 * s + 0];
        Whh[s] = (const float*)d_in[base + 3 * s + 1];
        bv[s]  = (const float*)d_in[base + 3 * s + 2];
    }
    const float* w_u = (const float*)d_in[iwu];
    const float* Wd  = (const float*)d_in[iwd];
    const float* bd  = (const float*)d_in[ibd];
    float* outp = (float*)d_out;

    zero_kernel<<<256, 256>>>();                              // covers 65536
    mark_kernel<<<(BATCH * (TBODY + TPUN)) / 256, 256>>>(body_idx, pun_idx);

    dim3 gg((VOCAB + BM - 1) / BM, 4, 2);
    gemm_tbl_kernel<<<gg, 256>>>(emb, Wih[0], Wih[1], Wih[2], Wih[3],
                                 bv[0], bv[1], bv[2], bv[3]);

    lstm_kernel<<<512, 256>>>(body_idx, pun_idx, Whh[0], Whh[1], Whh[2], Whh[3]);

    aux_kernel<<<BATCH, 256>>>(w_u);

    align_kernel<<<BATCH * 32, 256>>>(w_u);

    final_kernel<<<BATCH, 512>>>(Wd, bd, outp);
    (void)n_in; (void)out_size;
}

// round 16
// speedup vs baseline: 1.4974x; 1.0547x over previous
#include <cuda_runtime.h>
#include <cuda_bf16.h>
#include <mma.h>
#include <cstdint>

using namespace nvcuda;

#define VOCAB 50000
#define EMBD  300
#define HID   64
#define G4    256      // 4*H
#define D2    128      // 2*H
#define BATCH 128
#define TBODY 512
#define TPUN  256

// ---------------- scratch (static device arrays: allocation-free) ----------------
__device__ float    g_tbl[(size_t)4 * VOCAB * G4];          // 204.8 MB gate tables
__device__ float    g_bodyM[(size_t)BATCH * TBODY * D2];    // 33.5 MB
__device__ float    g_punM[(size_t)BATCH * TPUN * D2];      // 16.8 MB
__device__ unsigned g_rowmax[BATCH * TBODY];                // ordered-int encoded
__device__ unsigned g_colmax[BATCH * TPUN];                 // ordered-int encoded
__device__ float    g_a1[BATCH * TBODY];                    // w1 . bodyM row
__device__ float    g_a2[BATCH * TPUN];                     // w2 . punM row
__device__ int      g_flag[2][VOCAB];                       // 0 body, 1 pun
__device__ int      g_list[2][VOCAB];
__device__ int      g_cnt[2];
// W pre-split to bf16 hi/lo, K padded 300->320: [seg][split][n][k]
__device__ __align__(16) __nv_bfloat16 g_wbf[4][2][256][320];

// ---------------- helpers ----------------
__device__ __forceinline__ unsigned enc_f(float f) {
    unsigned u = __float_as_uint(f);
    return (u & 0x80000000u) ? ~u : (u | 0x80000000u);
}
__device__ __forceinline__ float dec_f(unsigned u) {
    return __uint_as_float((u & 0x80000000u) ? (u ^ 0x80000000u) : ~u);
}
__device__ __forceinline__ unsigned long long ffma2(unsigned long long a,
                                                    unsigned long long b,
                                                    unsigned long long c) {
    unsigned long long d;
    asm("fma.rn.f32x2 %0, %1, %2, %3;" : "=l"(d) : "l"(a), "l"(b), "l"(c));
    return d;
}
__device__ __forceinline__ unsigned long long pk2(float x) {
    unsigned long long r;
    asm("mov.b64 %0, {%1, %1};" : "=l"(r) : "f"(x));
    return r;
}
__device__ __forceinline__ float2 up2(unsigned long long p) {
    float2 r;
    asm("mov.b64 {%0, %1}, %2;" : "=f"(r.x), "=f"(r.y) : "l"(p));
    return r;
}
__device__ __forceinline__ float fast_sigmoid(float x) {
    return __fdividef(1.f, 1.f + __expf(-x));
}
__device__ __forceinline__ float fast_tanh(float x) {
    return 1.f - __fdividef(2.f, __expf(2.f * x) + 1.f);
}

// ---------------- kernel 0: zero flags/counters + encoded-max arrays ----------------
__global__ void zero_kernel() {
    int i = blockIdx.x * blockDim.x + threadIdx.x;   // grid covers 65536
    if (i < VOCAB) { g_flag[0][i] = 0; g_flag[1][i] = 0; }
    if (i == 0) { g_cnt[0] = 0; g_cnt[1] = 0; }
    if (i < BATCH * TBODY) g_rowmax[i] = 0u;
    if (i < BATCH * TPUN)  g_colmax[i] = 0u;
}

// ---------------- kernel 0b: mark used vocab ids, warp-aggregated compaction ------
__global__ void mark_kernel(const int* __restrict__ body_idx,
                            const int* __restrict__ pun_idx) {
    int i = blockIdx.x * blockDim.x + threadIdx.x;   // 98304 threads
    int which, v;
    if (i < BATCH * TBODY) { which = 0; v = body_idx[i]; }
    else                   { which = 1; v = pun_idx[i - BATCH * TBODY]; }
    bool isnew = (atomicExch(&g_flag[which][v], 1) == 0);
    unsigned mask = __ballot_sync(0xFFFFFFFFu, isnew);
    int n = __popc(mask);
    if (n) {
        int lane = threadIdx.x & 31;
        int leader = __ffs(mask) - 1;
        int base = 0;
        if (lane == leader) base = atomicAdd(&g_cnt[which], n);
        base = __shfl_sync(0xFFFFFFFFu, base, leader);
        if (isnew) g_list[which][base + __popc(mask & ((1u << lane) - 1))] = v;
    }
}

// ---------------- kernel 0c: pre-split W to bf16 hi/lo (K padded to 320) ----------
__global__ void prep_wbf_kernel(const float* __restrict__ W0, const float* __restrict__ W1,
                                const float* __restrict__ W2, const float* __restrict__ W3) {
    int i = blockIdx.x * blockDim.x + threadIdx.x;   // 4*256*320 = 327680 exact
    int k = i % 320;
    int n = (i / 320) & 255;
    int seg = i / (320 * 256);
    const float* W = (seg == 0) ? W0 : (seg == 1) ? W1 : (seg == 2) ? W2 : W3;
    float x = (k < EMBD) ? W[n * EMBD + k] : 0.f;
    __nv_bfloat16 hi = __float2bfloat16(x);
    float lo = x - __bfloat162float(hi);
    g_wbf[seg][0][n][k] = hi;
    g_wbf[seg][1][n][k] = __float2bfloat16(lo);
}

// ---------------- kernel 1: gate-table GEMM via WMMA bf16 3-way split -------------
// grid (391, 8, 2): x = 128-row m-block over used list; y = dir*4 + n-quarter
// (n0 = q*64); z = text type. Block 128 rows x 64 cols, 8 warps (warp tile 32x32).
// K in 5 chunks of 64; A gathered+hi/lo-split into smem; B copied from g_wbf.
// D = Ah*Bh + Ah*Bl + Al*Bh accumulated in fp32 wmma acc fragments.
#define ALD 72    // smem row stride for bf16 operands (multiple of 8)
#define PLD 20    // patch row stride for f32 accum store (MUST be multiple of 4)
__global__ void __launch_bounds__(256, 3) gemm_tbl_wmma(
    const float* __restrict__ emb,
    const float* __restrict__ B0, const float* __restrict__ B1,
    const float* __restrict__ B2, const float* __restrict__ B3)
{
    int z = blockIdx.z;
    int cnt = g_cnt[z];
    int m0 = blockIdx.x * 128;
    if (m0 >= cnt) return;
    int dir = blockIdx.y >> 2;
    int n0  = (blockIdx.y & 3) * 64;
    int seg = z * 2 + dir;
    const float* bias = (seg == 0) ? B0 : (seg == 1) ? B1 : (seg == 2) ? B2 : B3;
    float* out = g_tbl + (size_t)seg * VOCAB * G4;

    __shared__ __align__(16) __nv_bfloat16 Ahi[128][ALD];
    __shared__ __align__(16) __nv_bfloat16 Alo[128][ALD];
    __shared__ __align__(16) __nv_bfloat16 Bsm[2][64][ALD];   // [split][n][k]
    __shared__ __align__(16) float patch[8][16][PLD];
    __shared__ int ids[128];

    int tid = threadIdx.x;
    int warp = tid >> 5, lane = tid & 31;
    int wm = warp >> 1;          // 0..3 -> rows wm*32
    int wn = warp & 1;           // 0..1 -> cols wn*32

    if (tid < 128) ids[tid] = (m0 + tid < cnt) ? g_list[z][m0 + tid] : 0;
    __syncthreads();

    wmma::fragment<wmma::accumulator, 16, 16, 16, float> acc[2][2];
#pragma unroll
    for (int i = 0; i < 2; i++)
#pragma unroll
        for (int j = 0; j < 2; j++) wmma::fill_fragment(acc[i][j], 0.f);

    for (int ch = 0; ch < 5; ch++) {
        int k0 = ch * 64;
        // stage A: 128 rows x 32 float2 gathers, split hi/lo
#pragma unroll
        for (int i = 0; i < 16; i++) {
            int p = tid + 256 * i;            // < 4096
            int row = p >> 5, q = p & 31;
            int k = k0 + q * 2;
            float2 v = make_float2(0.f, 0.f);
            if (k < EMBD) v = *(const float2*)&emb[(size_t)ids[row] * EMBD + k];
            __nv_bfloat162 hi2 = __float22bfloat162_rn(v);
            float2 hb = make_float2(__low2float(hi2), __high2float(hi2));
            __nv_bfloat162 lo2 = __float22bfloat162_rn(make_float2(v.x - hb.x, v.y - hb.y));
            *(__nv_bfloat162*)&Ahi[row][q * 2] = hi2;
            *(__nv_bfloat162*)&Alo[row][q * 2] = lo2;
        }
        // stage B: 2 splits x 64 rows x 64 bf16, 16B copies
#pragma unroll
        for (int i = 0; i < 4; i++) {
            int u = tid + 256 * i;            // < 1024
            int split = u >> 9;
            int row = (u >> 3) & 63;
            int s8 = u & 7;
            *(uint4*)&Bsm[split][row][s8 * 8] =
                *(const uint4*)&g_wbf[seg][split][n0 + row][k0 + s8 * 8];
        }
        __syncthreads();

#pragma unroll
        for (int ks = 0; ks < 4; ks++) {
            wmma::fragment<wmma::matrix_a, 16, 16, 16, __nv_bfloat16, wmma::row_major> ah[2], al[2];
            wmma::fragment<wmma::matrix_b, 16, 16, 16, __nv_bfloat16, wmma::col_major> bh[2], bl[2];
#pragma unroll
            for (int fm = 0; fm < 2; fm++) {
                wmma::load_matrix_sync(ah[fm], &Ahi[wm * 32 + fm * 16][ks * 16], ALD);
                wmma::load_matrix_sync(al[fm], &Alo[wm * 32 + fm * 16][ks * 16], ALD);
            }
#pragma unroll
            for (int fn = 0; fn < 2; fn++) {
                wmma::load_matrix_sync(bh[fn], &Bsm[0][wn * 32 + fn * 16][ks * 16], ALD);
                wmma::load_matrix_sync(bl[fn], &Bsm[1][wn * 32 + fn * 16][ks * 16], ALD);
            }
#pragma unroll
            for (int fm = 0; fm < 2; fm++)
#pragma unroll
                for (int fn = 0; fn < 2; fn++) {
                    wmma::mma_sync(acc[fm][fn], ah[fm], bh[fn], acc[fm][fn]);
                    wmma::mma_sync(acc[fm][fn], ah[fm], bl[fn], acc[fm][fn]);
                    wmma::mma_sync(acc[fm][fn], al[fm], bh[fn], acc[fm][fn]);
                }
        }
        __syncthreads();
    }

    // epilogue: per-warp patch (ld=PLD, multiple of 4), add bias, write f32 rows
#pragma unroll
    for (int fm = 0; fm < 2; fm++)
#pragma unroll
        for (int fn = 0; fn < 2; fn++) {
            wmma::store_matrix_sync(&patch[warp][0][0], acc[fm][fn], PLD, wmma::mem_row_major);
            __syncwarp();
            int r = lane >> 1;                 // 0..15
            int c0 = (lane & 1) * 8;           // 0 or 8
            int grow = ids[wm * 32 + fm * 16 + r];
            int col = n0 + wn * 32 + fn * 16 + c0;
            float* orow = out + (size_t)grow * G4 + col;
#pragma unroll
            for (int c = 0; c < 8; c++)
                orow[c] = patch[warp][r][c0 + c] + bias[col + c];
            __syncwarp();
        }
}

// ---------------- kernel 2: LSTM (R9 structure + fast activations) ----------------
__global__ void __launch_bounds__(256, 2) lstm_kernel(
    const int* __restrict__ body_idx, const int* __restrict__ pun_idx,
    const float* __restrict__ Whh0, const float* __restrict__ Whh1,
    const float* __restrict__ Whh2, const float* __restrict__ Whh3)
{
    int blk = blockIdx.x;
    int seg = (blk >> 7) ^ 2;        // schedule puns (short) first
    int b   = blk & 127;
    bool isBody = (seg < 2);
    bool isFwd  = ((seg & 1) == 0);
    int T = isBody ? TBODY : TPUN;
    const int* idx = isBody ? (body_idx + b * TBODY) : (pun_idx + b * TPUN);
    const float* Whh = (seg == 0) ? Whh0 : (seg == 1) ? Whh1 : (seg == 2) ? Whh2 : Whh3;
    const float* tbl = g_tbl + (size_t)seg * VOCAB * G4;
    float* out = isBody ? (g_bodyM + (size_t)b * TBODY * D2)
                        : (g_punM  + (size_t)b * TPUN  * D2);
    int off = isFwd ? 0 : HID;

    __shared__ int idx_s[TBODY];
    __shared__ __align__(16) float hs[2][HID];
    __shared__ int len_s;

    int tid  = threadIdx.x;
    int lane = tid & 31;
    int warp = tid >> 5;
    int gc   = lane >> 3;                 // gate class: 0=i,1=f,2=g,3=o
    int u    = (warp << 3) | (lane & 7);  // hidden unit 0..63
    int r    = gc * HID + u;              // gate row 0..255

    if (tid == 0) len_s = 0;
    if (tid < HID) { hs[0][tid] = 0.f; hs[1][tid] = 0.f; }
    __syncthreads();

    int cnt = 0;
    for (int t = tid; t < T; t += 256) {
        int v = idx[t];
        idx_s[t] = v;
        cnt += (v != 0);
    }
#pragma unroll
    for (int o = 16; o; o >>= 1) cnt += __shfl_xor_sync(0xFFFFFFFFu, cnt, o);
    if (lane == 0) atomicAdd(&len_s, cnt);
    __syncthreads();
    int len = len_s;

    unsigned long long wp[32];
    {
        const unsigned long long* wr = (const unsigned long long*)(Whh + (size_t)r * HID);
#pragma unroll
        for (int j = 0; j < 32; j++) wp[j] = wr[j];
    }

    float c = 0.f;
    float x1 = 0.f, x2 = 0.f;
    if (len > 0) x1 = tbl[(size_t)idx_s[isFwd ? 0 : (len - 1)] * G4 + r];
    if (len > 1) x2 = tbl[(size_t)idx_s[isFwd ? 1 : (len - 2)] * G4 + r];

    for (int t = 0; t < len; t++) {
        float xs = x1;
        x1 = x2;
        if (t + 2 < len) {
            int p2 = isFwd ? (t + 2) : (len - 3 - t);
            x2 = tbl[(size_t)idx_s[p2] * G4 + r];
        }
        const ulonglong2* hp = (const ulonglong2*)hs[t & 1];
        unsigned long long a0 = 0ull, a1 = 0ull, a2 = 0ull, a3 = 0ull;
#pragma unroll
        for (int jj = 0; jj < 8; jj++) {
            ulonglong2 hA = hp[2 * jj];
            ulonglong2 hB = hp[2 * jj + 1];
            a0 = ffma2(wp[4 * jj + 0], hA.x, a0);
            a1 = ffma2(wp[4 * jj + 1], hA.y, a1);
            a2 = ffma2(wp[4 * jj + 2], hB.x, a2);
            a3 = ffma2(wp[4 * jj + 3], hB.y, a3);
        }
        float2 s0 = up2(a0), s1 = up2(a1), s2 = up2(a2), s3 = up2(a3);
        float pre = xs + ((s0.x + s0.y) + (s1.x + s1.y))
                       + ((s2.x + s2.y) + (s3.x + s3.y));
        float act = (gc == 2) ? fast_tanh(pre) : fast_sigmoid(pre);
        float fA = __shfl_sync(0xFFFFFFFFu, act, (lane + 8) & 31);
        float gA = __shfl_sync(0xFFFFFFFFu, act, (lane + 16) & 31);
        float oA = __shfl_sync(0xFFFFFFFFu, act, (lane + 24) & 31);
        if (gc == 0) {
            c = fA * c + act * gA;          // act = i-gate
            float h = oA * fast_tanh(c);
            hs[(t + 1) & 1][u] = h;
            int pos = isFwd ? t : (len - 1 - t);
            out[(size_t)pos * D2 + off + u] = h;
        }
        __syncthreads();
    }
    for (int l = tid; l < (T - len) * HID; l += 256) {
        int tpos = len + l / HID;
        int j = l - (l / HID) * HID;
        out[(size_t)tpos * D2 + off + j] = 0.f;
    }
}

// ---------------- kernel 2b: aux row-dots a1 = w1.body, a2 = w2.pun ---------------
__global__ void __launch_bounds__(256) aux_kernel(const float* __restrict__ w_u)
{
    int b = blockIdx.x;
    int tid = threadIdx.x;
    int lane = tid & 31, warp = tid >> 5;

    float4 w1v = *(const float4*)&w_u[lane * 4];
    float4 w2v = *(const float4*)&w_u[D2 + lane * 4];

    const float* bm = g_bodyM + (size_t)b * TBODY * D2;
    for (int r = warp; r < TBODY; r += 8) {
        float4 x = *(const float4*)&bm[(size_t)r * D2 + lane * 4];
        float s = x.x * w1v.x + x.y * w1v.y + x.z * w1v.z + x.w * w1v.w;
#pragma unroll
        for (int o = 16; o; o >>= 1) s += __shfl_xor_sync(0xFFFFFFFFu, s, o);
        if (lane == 0) g_a1[b * TBODY + r] = s;
    }
    const float* pm = g_punM + (size_t)b * TPUN * D2;
    for (int r = warp; r < TPUN; r += 8) {
        float4 x = *(const float4*)&pm[(size_t)r * D2 + lane * 4];
        float s = x.x * w2v.x + x.y * w2v.y + x.z * w2v.z + x.w * w2v.w;
#pragma unroll
        for (int o = 16; o; o >>= 1) s += __shfl_xor_sync(0xFFFFFFFFu, s, o);
        if (lane == 0) g_a2[b * TPUN + r] = s;
    }
}

// ---------------- kernel 3: alignment maxes, 64x64 tiles, 4 blocks/SM -------------
#define ABK 16
__global__ void __launch_bounds__(256, 4) align_kernel(const float* __restrict__ w_u)
{
    int bx = blockIdx.x;
    int b  = bx >> 5;
    int tc = (bx >> 2) & 7;
    int pc = bx & 3;
    int t0 = tc * 64;
    int p0 = pc * 64;
    const float* bodyM = g_bodyM + (size_t)b * TBODY * D2;
    const float* punM  = g_punM  + (size_t)b * TPUN  * D2;

    __shared__ __align__(16) unsigned long long Bsu[2][ABK][66];
    __shared__ __align__(16) float Ps[2][ABK][68];
    __shared__ unsigned rms[64], cms[64];

    int tid = threadIdx.x;
    int tx = tid & 15, ty = tid >> 4;
    int q  = tid & 3;
    int rr = tid >> 2;

    if (tid < 64) { rms[tid] = 0u; cms[tid] = 0u; }

    unsigned long long acc[4][2];
#pragma unroll
    for (int i = 0; i < 4; i++) { acc[i][0] = 0ull; acc[i][1] = 0ull; }

    float4 bv, pv;
    {
        float4 w3v = *(const float4*)&w_u[2 * D2 + 4 * q];
        float4 v = *(const float4*)&bodyM[(size_t)(t0 + rr) * D2 + 4 * q];
        bv = make_float4(v.x * w3v.x, v.y * w3v.y, v.z * w3v.z, v.w * w3v.w);
        pv = *(const float4*)&punM[(size_t)(p0 + rr) * D2 + 4 * q];
    }

    for (int kc = 0; kc < 8; kc++) {
        int buf = kc & 1;
        Bsu[buf][4 * q + 0][rr] = pk2(bv.x);
        Bsu[buf][4 * q + 1][rr] = pk2(bv.y);
        Bsu[buf][4 * q + 2][rr] = pk2(bv.z);
        Bsu[buf][4 * q + 3][rr] = pk2(bv.w);
        Ps[buf][4 * q + 0][rr] = pv.x;
        Ps[buf][4 * q + 1][rr] = pv.y;
        Ps[buf][4 * q + 2][rr] = pv.z;
        Ps[buf][4 * q + 3][rr] = pv.w;
        __syncthreads();
        if (kc < 7) {
            int d0 = (kc + 1) * ABK;
            float4 w3v = *(const float4*)&w_u[2 * D2 + d0 + 4 * q];
            float4 v = *(const float4*)&bodyM[(size_t)(t0 + rr) * D2 + d0 + 4 * q];
            bv = make_float4(v.x * w3v.x, v.y * w3v.y, v.z * w3v.z, v.w * w3v.w);
            pv = *(const float4*)&punM[(size_t)(p0 + rr) * D2 + d0 + 4 * q];
        }
#pragma unroll
        for (int d = 0; d < ABK; d++) {
            ulonglong2 a01 = *(const ulonglong2*)&Bsu[buf][d][ty * 4];
            ulonglong2 a23 = *(const ulonglong2*)&Bsu[buf][d][ty * 4 + 2];
            ulonglong2 bb  = *(const ulonglong2*)&Ps[buf][d][tx * 4];
            acc[0][0] = ffma2(a01.x, bb.x, acc[0][0]);
            acc[0][1] = ffma2(a01.x, bb.y, acc[0][1]);
            acc[1][0] = ffma2(a01.y, bb.x, acc[1][0]);
            acc[1][1] = ffma2(a01.y, bb.y, acc[1][1]);
            acc[2][0] = ffma2(a23.x, bb.x, acc[2][0]);
            acc[2][1] = ffma2(a23.x, bb.y, acc[2][1]);
            acc[3][0] = ffma2(a23.y, bb.x, acc[3][0]);
            acc[3][1] = ffma2(a23.y, bb.y, acc[3][1]);
        }
    }

    float a2v[4];
#pragma unroll
    for (int j = 0; j < 4; j++) a2v[j] = g_a2[b * TPUN + p0 + tx * 4 + j];

    float cmax[4];
#pragma unroll
    for (int j = 0; j < 4; j++) cmax[j] = -1e30f;
#pragma unroll
    for (int i = 0; i < 4; i++) {
        float a1v = g_a1[b * TBODY + t0 + ty * 4 + i];
        float rmax = -1e30f;
#pragma unroll
        for (int j2 = 0; j2 < 2; j2++) {
            float2 v = up2(acc[i][j2]);
            float v0 = v.x + a1v + a2v[j2 * 2];
            float v1 = v.y + a1v + a2v[j2 * 2 + 1];
            rmax = fmaxf(rmax, fmaxf(v0, v1));
            cmax[j2 * 2]     = fmaxf(cmax[j2 * 2], v0);
            cmax[j2 * 2 + 1] = fmaxf(cmax[j2 * 2 + 1], v1);
        }
        atomicMax(&rms[ty * 4 + i], enc_f(rmax));
    }
#pragma unroll
    for (int j = 0; j < 4; j++)
        atomicMax(&cms[tx * 4 + j], enc_f(cmax[j]));
    __syncthreads();

    if (tid < 64) {
        atomicMax(&g_rowmax[b * TBODY + t0 + tid], rms[tid]);
        atomicMax(&g_colmax[b * TPUN + p0 + tid], cms[tid]);
    }
}

// ---------------- kernel 4: softmaxes + weighted sums + final linear (512 thr) ----
__global__ void __launch_bounds__(512) final_kernel(
    const float* __restrict__ Wd, const float* __restrict__ bd,
    float* __restrict__ outp)
{
    int b = blockIdx.x;
    int tid = threadIdx.x;
    int lane = tid & 31, warp = tid >> 5;   // 16 warps

    __shared__ float attb[TBODY];
    __shared__ float attp[TPUN];
    __shared__ float part[512];
    __shared__ float feat[G4];
    __shared__ float sred[16];

    float v = dec_f(g_rowmax[b * TBODY + tid]);
    float m = v;
#pragma unroll
    for (int o = 16; o; o >>= 1) m = fmaxf(m, __shfl_xor_sync(0xFFFFFFFFu, m, o));
    if (lane == 0) sred[warp] = m;
    __syncthreads();
    float M = sred[0];
#pragma unroll
    for (int w = 1; w < 16; w++) M = fmaxf(M, sred[w]);
    __syncthreads();
    float e = __expf(v - M);
    float ss = e;
#pragma unroll
    for (int o = 16; o; o >>= 1) ss += __shfl_xor_sync(0xFFFFFFFFu, ss, o);
    if (lane == 0) sred[warp] = ss;
    __syncthreads();
    float S = 0.f;
#pragma unroll
    for (int w = 0; w < 16; w++) S += sred[w];
    __syncthreads();
    attb[tid] = e / S;

    float u = (tid < TPUN) ? dec_f(g_colmax[b * TPUN + tid]) : -1e30f;
    float m2 = u;
#pragma unroll
    for (int o = 16; o; o >>= 1) m2 = fmaxf(m2, __shfl_xor_sync(0xFFFFFFFFu, m2, o));
    if (lane == 0) sred[warp] = m2;
    __syncthreads();
    float M2 = sred[0];
#pragma unroll
    for (int w = 1; w < 16; w++) M2 = fmaxf(M2, sred[w]);
    __syncthreads();
    float e2 = (tid < TPUN) ? __expf(u - M2) : 0.f;
    float ss2 = e2;
#pragma unroll
    for (int o = 16; o; o >>= 1) ss2 += __shfl_xor_sync(0xFFFFFFFFu, ss2, o);
    if (lane == 0) sred[warp] = ss2;
    __syncthreads();
    float S2 = 0.f;
#pragma unroll
    for (int w = 0; w < 16; w++) S2 += sred[w];
    if (tid < TPUN) attp[tid] = e2 / S2;
    __syncthreads();

    int col = tid & 255, half = tid >> 8;
    float s = 0.f;
    if (col < D2) {
        const float* bm = g_bodyM + (size_t)b * TBODY * D2 + col;
        int tbeg = half * 256, tend = tbeg + 256;
#pragma unroll 8
        for (int t = tbeg; t < tend; t++) s += bm[(size_t)t * D2] * attb[t];
    } else {
        int d = col - D2;
        const float* pm = g_punM + (size_t)b * TPUN * D2 + d;
        int pbeg = half * 128, pend = pbeg + 128;
#pragma unroll 8
        for (int p = pbeg; p < pend; p++) s += pm[(size_t)p * D2] * attp[p];
    }
    part[tid] = s;
    __syncthreads();
    if (tid < G4) feat[tid] = part[tid] + part[tid + 256];
    __syncthreads();

    if (tid < 3) {
        float sum = bd[tid];
        for (int k = 0; k < G4; k++) sum += feat[k] * Wd[tid * G4 + k];
        outp[b * 3 + tid] = sum;
    }
}

// ---------------- host launcher ----------------
extern "C" void kernel_launch(void* const* d_in, const int* in_sizes, int n_in,
                              void* d_out, int out_size)
{
    int base, iwu, iwd, ibd;
    if (in_sizes[3] == 76800) { base = 3; iwu = 15; iwd = 16; ibd = 17; }
    else                      { base = 6; iwu = 3;  iwd = 4;  ibd = 5;  }

    const int*   body_idx = (const int*)d_in[0];
    const int*   pun_idx  = (const int*)d_in[1];
    const float* emb      = (const float*)d_in[2];

    const float* Wih[4]; const float* Whh[4]; const float* bv[4];
    for (int s = 0; s < 4; s++) {
        Wih[s] = (const float*)d_in[base + 3 * s + 0];
        Whh[s] = (const float*)d_in[base + 3 * s + 1];
        bv[s]  = (const float*)d_in[base + 3 * s + 2];
    }
    const float* w_u = (const float*)d_in[iwu];
    const float* Wd  = (const float*)d_in[iwd];
    const float* bd  = (const float*)d_in[ibd];
    float* outp = (float*)d_out;

    zero_kernel<<<256, 256>>>();
    mark_kernel<<<(BATCH * (TBODY + TPUN)) / 256, 256>>>(body_idx, pun_idx);
    prep_wbf_kernel<<<1280, 256>>>(Wih[0], Wih[1], Wih[2], Wih[3]);

    dim3 gg((VOCAB + 127) / 128, 8, 2);
    gemm_tbl_wmma<<<gg, 256>>>(emb, bv[0], bv[1], bv[2], bv[3]);

    lstm_kernel<<<512, 256>>>(body_idx, pun_idx, Whh[0], Whh[1], Whh[2], Whh[3]);

    aux_kernel<<<BATCH, 256>>>(w_u);

    align_kernel<<<BATCH * 32, 256>>>(w_u);

    final_kernel<<<BATCH, 512>>>(Wd, bd, outp);
    (void)n_in; (void)out_size;
}

// round 17
// speedup vs baseline: 1.6145x; 1.0782x over previous
#include <cuda_runtime.h>
#include <cuda_bf16.h>
#include <mma.h>
#include <cstdint>

using namespace nvcuda;

#define VOCAB 50000
#define EMBD  300
#define HID   64
#define G4    256      // 4*H
#define D2    128      // 2*H
#define BATCH 128
#define TBODY 512
#define TPUN  256
#define MROWS 50048    // 391*128 padded used-row capacity

// ---------------- scratch (static device arrays: allocation-free) ----------------
__device__ float    g_tbl[(size_t)4 * VOCAB * G4];          // 204.8 MB gate tables
__device__ float    g_bodyM[(size_t)BATCH * TBODY * D2];    // 33.5 MB
__device__ float    g_punM[(size_t)BATCH * TPUN * D2];      // 16.8 MB
__device__ unsigned g_rowmax[BATCH * TBODY];                // ordered-int encoded
__device__ unsigned g_colmax[BATCH * TPUN];                 // ordered-int encoded
__device__ float    g_a1[BATCH * TBODY];                    // w1 . bodyM row
__device__ float    g_a2[BATCH * TPUN];                     // w2 . punM row
__device__ int      g_flag[2][VOCAB];                       // 0 body, 1 pun
__device__ int      g_list[2][VOCAB];
__device__ int      g_cnt[2];
// W pre-split to bf16 hi/lo, K padded 300->320: [seg][split][n][k]
__device__ __align__(16) __nv_bfloat16 g_wbf[4][2][256][320];
// emb gathered+split per used row: [type][split][row][k]  (128.1 MB)
__device__ __align__(16) __nv_bfloat16 g_abf[2][2][MROWS][320];

// ---------------- helpers ----------------
__device__ __forceinline__ unsigned enc_f(float f) {
    unsigned u = __float_as_uint(f);
    return (u & 0x80000000u) ? ~u : (u | 0x80000000u);
}
__device__ __forceinline__ float dec_f(unsigned u) {
    return __uint_as_float((u & 0x80000000u) ? (u ^ 0x80000000u) : ~u);
}
__device__ __forceinline__ unsigned long long ffma2(unsigned long long a,
                                                    unsigned long long b,
                                                    unsigned long long c) {
    unsigned long long d;
    asm("fma.rn.f32x2 %0, %1, %2, %3;" : "=l"(d) : "l"(a), "l"(b), "l"(c));
    return d;
}
__device__ __forceinline__ unsigned long long pk2(float x) {
    unsigned long long r;
    asm("mov.b64 %0, {%1, %1};" : "=l"(r) : "f"(x));
    return r;
}
__device__ __forceinline__ float2 up2(unsigned long long p) {
    float2 r;
    asm("mov.b64 {%0, %1}, %2;" : "=f"(r.x), "=f"(r.y) : "l"(p));
    return r;
}
__device__ __forceinline__ float fast_sigmoid(float x) {
    return __fdividef(1.f, 1.f + __expf(-x));
}
__device__ __forceinline__ float fast_tanh(float x) {
    return 1.f - __fdividef(2.f, __expf(2.f * x) + 1.f);
}

// ---------------- kernel 0: zero flags/counters + encoded-max arrays ----------------
__global__ void zero_kernel() {
    int i = blockIdx.x * blockDim.x + threadIdx.x;   // grid covers 65536
    if (i < VOCAB) { g_flag[0][i] = 0; g_flag[1][i] = 0; }
    if (i == 0) { g_cnt[0] = 0; g_cnt[1] = 0; }
    if (i < BATCH * TBODY) g_rowmax[i] = 0u;
    if (i < BATCH * TPUN)  g_colmax[i] = 0u;
}

// ---------------- kernel 0b: mark used vocab ids, warp-aggregated compaction ------
__global__ void mark_kernel(const int* __restrict__ body_idx,
                            const int* __restrict__ pun_idx) {
    int i = blockIdx.x * blockDim.x + threadIdx.x;   // 98304 threads
    int which, v;
    if (i < BATCH * TBODY) { which = 0; v = body_idx[i]; }
    else                   { which = 1; v = pun_idx[i - BATCH * TBODY]; }
    bool isnew = (atomicExch(&g_flag[which][v], 1) == 0);
    unsigned mask = __ballot_sync(0xFFFFFFFFu, isnew);
    int n = __popc(mask);
    if (n) {
        int lane = threadIdx.x & 31;
        int leader = __ffs(mask) - 1;
        int base = 0;
        if (lane == leader) base = atomicAdd(&g_cnt[which], n);
        base = __shfl_sync(0xFFFFFFFFu, base, leader);
        if (isnew) g_list[which][base + __popc(mask & ((1u << lane) - 1))] = v;
    }
}

// ---------------- kernel 0c: pre-split W to bf16 hi/lo (K padded to 320) ----------
__global__ void prep_wbf_kernel(const float* __restrict__ W0, const float* __restrict__ W1,
                                const float* __restrict__ W2, const float* __restrict__ W3) {
    int i = blockIdx.x * blockDim.x + threadIdx.x;   // 4*256*320 = 327680 exact
    int k = i % 320;
    int n = (i / 320) & 255;
    int seg = i / (320 * 256);
    const float* W = (seg == 0) ? W0 : (seg == 1) ? W1 : (seg == 2) ? W2 : W3;
    float x = (k < EMBD) ? W[n * EMBD + k] : 0.f;
    __nv_bfloat16 hi = __float2bfloat16(x);
    float lo = x - __bfloat162float(hi);
    g_wbf[seg][0][n][k] = hi;
    g_wbf[seg][1][n][k] = __float2bfloat16(lo);
}

// ---------------- kernel 0d: gather + split used emb rows to g_abf ----------------
// grid (391, 2): 128 rows per block; warp per row-set; lane covers k-pairs.
__global__ void __launch_bounds__(256) aprep_kernel(const float* __restrict__ emb) {
    int z = blockIdx.y;
    int cnt = g_cnt[z];
    int m0 = blockIdx.x * 128;
    if (m0 >= cnt) return;
    int tid = threadIdx.x, lane = tid & 31, warp = tid >> 5;
    for (int rr = warp; rr < 128; rr += 8) {
        int row = m0 + rr;
        int id = (row < cnt) ? g_list[z][row] : 0;
        const float* er = emb + (size_t)id * EMBD;
#pragma unroll
        for (int it = 0; it < 5; it++) {
            int q = lane + 32 * it;        // pair index 0..159
            int k = q * 2;
            float2 v = (k < EMBD) ? *(const float2*)&er[k] : make_float2(0.f, 0.f);
            __nv_bfloat162 hi2 = __float22bfloat162_rn(v);
            float2 hb = make_float2(__low2float(hi2), __high2float(hi2));
            __nv_bfloat162 lo2 = __float22bfloat162_rn(make_float2(v.x - hb.x, v.y - hb.y));
            *(__nv_bfloat162*)&g_abf[z][0][row][k] = hi2;
            *(__nv_bfloat162*)&g_abf[z][1][row][k] = lo2;
        }
    }
}

// ---------------- kernel 1: gate-table GEMM via WMMA bf16 3-way split -------------
// grid (391, 8, 2): x = 128-row m-block; y = dir*4 + n-quarter; z = type.
// Block 128x64, 8 warps (warp tile 32x32). K in 5 chunks of 64.
// A staged from precomputed g_abf via uint4 copies with REGISTER PREFETCH of the
// next chunk (LDG latency hidden under MMA); B direct-staged from g_wbf (L2-hot).
#define ALD 72    // smem row stride for bf16 operands (multiple of 8)
#define PLD 20    // patch row stride for f32 accum store (multiple of 4)
__global__ void __launch_bounds__(256, 2) gemm_tbl_wmma(
    const float* __restrict__ B0, const float* __restrict__ B1,
    const float* __restrict__ B2, const float* __restrict__ B3)
{
    int z = blockIdx.z;
    int cnt = g_cnt[z];
    int m0 = blockIdx.x * 128;
    if (m0 >= cnt) return;
    int dir = blockIdx.y >> 2;
    int n0  = (blockIdx.y & 3) * 64;
    int seg = z * 2 + dir;
    const float* bias = (seg == 0) ? B0 : (seg == 1) ? B1 : (seg == 2) ? B2 : B3;
    float* out = g_tbl + (size_t)seg * VOCAB * G4;

    __shared__ __align__(16) __nv_bfloat16 Ahi[128][ALD];
    __shared__ __align__(16) __nv_bfloat16 Alo[128][ALD];
    __shared__ __align__(16) __nv_bfloat16 Bsm[2][64][ALD];   // [split][n][k]
    __shared__ __align__(16) float patch[8][16][PLD];
    __shared__ int ids[128];

    int tid = threadIdx.x;
    int warp = tid >> 5, lane = tid & 31;
    int wm = warp >> 1;          // 0..3 -> rows wm*32
    int wn = warp & 1;           // 0..1 -> cols wn*32

    if (tid < 128) ids[tid] = (m0 + tid < cnt) ? g_list[z][m0 + tid] : 0;

    // A prefetch thread mapping: u = tid + 256*i (i<8) -> split/row/s8
    int asplit[8], arow[8], as8[8];
#pragma unroll
    for (int i = 0; i < 8; i++) {
        int u = tid + 256 * i;           // < 2048
        asplit[i] = u >> 10;
        arow[i]   = (u >> 3) & 127;
        as8[i]    = u & 7;
    }

    wmma::fragment<wmma::accumulator, 16, 16, 16, float> acc[2][2];
#pragma unroll
    for (int i = 0; i < 2; i++)
#pragma unroll
        for (int j = 0; j < 2; j++) wmma::fill_fragment(acc[i][j], 0.f);

    // prefetch chunk 0 A into registers
    uint4 ra[8];
#pragma unroll
    for (int i = 0; i < 8; i++)
        ra[i] = *(const uint4*)&g_abf[z][asplit[i]][m0 + arow[i]][as8[i] * 8];

    for (int ch = 0; ch < 5; ch++) {
        int k0 = ch * 64;
        // store prefetched A regs -> smem
#pragma unroll
        for (int i = 0; i < 8; i++) {
            __nv_bfloat16* dst = asplit[i] ? &Alo[arow[i]][as8[i] * 8]
                                           : &Ahi[arow[i]][as8[i] * 8];
            *(uint4*)dst = ra[i];
        }
        // stage B direct (L2-hot small table)
#pragma unroll
        for (int i = 0; i < 4; i++) {
            int u = tid + 256 * i;            // < 1024
            int split = u >> 9;
            int row = (u >> 3) & 63;
            int s8 = u & 7;
            *(uint4*)&Bsm[split][row][s8 * 8] =
                *(const uint4*)&g_wbf[seg][split][n0 + row][k0 + s8 * 8];
        }
        __syncthreads();
        // prefetch next chunk A (LDGs overlap the MMA phase below)
        if (ch < 4) {
            int k1 = k0 + 64;
#pragma unroll
            for (int i = 0; i < 8; i++)
                ra[i] = *(const uint4*)&g_abf[z][asplit[i]][m0 + arow[i]][k1 + as8[i] * 8];
        }

#pragma unroll
        for (int ks = 0; ks < 4; ks++) {
            wmma::fragment<wmma::matrix_a, 16, 16, 16, __nv_bfloat16, wmma::row_major> ah[2], al[2];
            wmma::fragment<wmma::matrix_b, 16, 16, 16, __nv_bfloat16, wmma::col_major> bh[2], bl[2];
#pragma unroll
            for (int fm = 0; fm < 2; fm++) {
                wmma::load_matrix_sync(ah[fm], &Ahi[wm * 32 + fm * 16][ks * 16], ALD);
                wmma::load_matrix_sync(al[fm], &Alo[wm * 32 + fm * 16][ks * 16], ALD);
            }
#pragma unroll
            for (int fn = 0; fn < 2; fn++) {
                wmma::load_matrix_sync(bh[fn], &Bsm[0][wn * 32 + fn * 16][ks * 16], ALD);
                wmma::load_matrix_sync(bl[fn], &Bsm[1][wn * 32 + fn * 16][ks * 16], ALD);
            }
#pragma unroll
            for (int fm = 0; fm < 2; fm++)
#pragma unroll
                for (int fn = 0; fn < 2; fn++) {
                    wmma::mma_sync(acc[fm][fn], ah[fm], bh[fn], acc[fm][fn]);
                    wmma::mma_sync(acc[fm][fn], ah[fm], bl[fn], acc[fm][fn]);
                    wmma::mma_sync(acc[fm][fn], al[fm], bh[fn], acc[fm][fn]);
                }
        }
        __syncthreads();
    }

    // epilogue: per-warp patch (ld=PLD), add bias, write f32 rows
#pragma unroll
    for (int fm = 0; fm < 2; fm++)
#pragma unroll
        for (int fn = 0; fn < 2; fn++) {
            wmma::store_matrix_sync(&patch[warp][0][0], acc[fm][fn], PLD, wmma::mem_row_major);
            __syncwarp();
            int r = lane >> 1;                 // 0..15
            int c0 = (lane & 1) * 8;           // 0 or 8
            int grow = ids[wm * 32 + fm * 16 + r];
            int col = n0 + wn * 32 + fn * 16 + c0;
            float* orow = out + (size_t)grow * G4 + col;
#pragma unroll
            for (int c = 0; c < 8; c++)
                orow[c] = patch[warp][r][c0 + c] + bias[col + c];
            __syncwarp();
        }
}

// ---------------- kernel 2: LSTM (R9 structure + fast activations) ----------------
__global__ void __launch_bounds__(256, 2) lstm_kernel(
    const int* __restrict__ body_idx, const int* __restrict__ pun_idx,
    const float* __restrict__ Whh0, const float* __restrict__ Whh1,
    const float* __restrict__ Whh2, const float* __restrict__ Whh3)
{
    int blk = blockIdx.x;
    int seg = (blk >> 7) ^ 2;        // schedule puns (short) first
    int b   = blk & 127;
    bool isBody = (seg < 2);
    bool isFwd  = ((seg & 1) == 0);
    int T = isBody ? TBODY : TPUN;
    const int* idx = isBody ? (body_idx + b * TBODY) : (pun_idx + b * TPUN);
    const float* Whh = (seg == 0) ? Whh0 : (seg == 1) ? Whh1 : (seg == 2) ? Whh2 : Whh3;
    const float* tbl = g_tbl + (size_t)seg * VOCAB * G4;
    float* out = isBody ? (g_bodyM + (size_t)b * TBODY * D2)
                        : (g_punM  + (size_t)b * TPUN  * D2);
    int off = isFwd ? 0 : HID;

    __shared__ int idx_s[TBODY];
    __shared__ __align__(16) float hs[2][HID];
    __shared__ int len_s;

    int tid  = threadIdx.x;
    int lane = tid & 31;
    int warp = tid >> 5;
    int gc   = lane >> 3;                 // gate class: 0=i,1=f,2=g,3=o
    int u    = (warp << 3) | (lane & 7);  // hidden unit 0..63
    int r    = gc * HID + u;              // gate row 0..255

    if (tid == 0) len_s = 0;
    if (tid < HID) { hs[0][tid] = 0.f; hs[1][tid] = 0.f; }
    __syncthreads();

    int cnt = 0;
    for (int t = tid; t < T; t += 256) {
        int v = idx[t];
        idx_s[t] = v;
        cnt += (v != 0);
    }
#pragma unroll
    for (int o = 16; o; o >>= 1) cnt += __shfl_xor_sync(0xFFFFFFFFu, cnt, o);
    if (lane == 0) atomicAdd(&len_s, cnt);
    __syncthreads();
    int len = len_s;

    unsigned long long wp[32];
    {
        const unsigned long long* wr = (const unsigned long long*)(Whh + (size_t)r * HID);
#pragma unroll
        for (int j = 0; j < 32; j++) wp[j] = wr[j];
    }

    float c = 0.f;
    float x1 = 0.f, x2 = 0.f;
    if (len > 0) x1 = tbl[(size_t)idx_s[isFwd ? 0 : (len - 1)] * G4 + r];
    if (len > 1) x2 = tbl[(size_t)idx_s[isFwd ? 1 : (len - 2)] * G4 + r];

    for (int t = 0; t < len; t++) {
        float xs = x1;
        x1 = x2;
        if (t + 2 < len) {
            int p2 = isFwd ? (t + 2) : (len - 3 - t);
            x2 = tbl[(size_t)idx_s[p2] * G4 + r];
        }
        const ulonglong2* hp = (const ulonglong2*)hs[t & 1];
        unsigned long long a0 = 0ull, a1 = 0ull, a2 = 0ull, a3 = 0ull;
#pragma unroll
        for (int jj = 0; jj < 8; jj++) {
            ulonglong2 hA = hp[2 * jj];
            ulonglong2 hB = hp[2 * jj + 1];
            a0 = ffma2(wp[4 * jj + 0], hA.x, a0);
            a1 = ffma2(wp[4 * jj + 1], hA.y, a1);
            a2 = ffma2(wp[4 * jj + 2], hB.x, a2);
            a3 = ffma2(wp[4 * jj + 3], hB.y, a3);
        }
        float2 s0 = up2(a0), s1 = up2(a1), s2 = up2(a2), s3 = up2(a3);
        float pre = xs + ((s0.x + s0.y) + (s1.x + s1.y))
                       + ((s2.x + s2.y) + (s3.x + s3.y));
        float act = (gc == 2) ? fast_tanh(pre) : fast_sigmoid(pre);
        float fA = __shfl_sync(0xFFFFFFFFu, act, (lane + 8) & 31);
        float gA = __shfl_sync(0xFFFFFFFFu, act, (lane + 16) & 31);
        float oA = __shfl_sync(0xFFFFFFFFu, act, (lane + 24) & 31);
        if (gc == 0) {
            c = fA * c + act * gA;          // act = i-gate
            float h = oA * fast_tanh(c);
            hs[(t + 1) & 1][u] = h;
            int pos = isFwd ? t : (len - 1 - t);
            out[(size_t)pos * D2 + off + u] = h;
        }
        __syncthreads();
    }
    for (int l = tid; l < (T - len) * HID; l += 256) {
        int tpos = len + l / HID;
        int j = l - (l / HID) * HID;
        out[(size_t)tpos * D2 + off + j] = 0.f;
    }
}

// ---------------- kernel 2b: aux row-dots a1 = w1.body, a2 = w2.pun ---------------
__global__ void __launch_bounds__(256) aux_kernel(const float* __restrict__ w_u)
{
    int b = blockIdx.x;
    int tid = threadIdx.x;
    int lane = tid & 31, warp = tid >> 5;

    float4 w1v = *(const float4*)&w_u[lane * 4];
    float4 w2v = *(const float4*)&w_u[D2 + lane * 4];

    const float* bm = g_bodyM + (size_t)b * TBODY * D2;
    for (int r = warp; r < TBODY; r += 8) {
        float4 x = *(const float4*)&bm[(size_t)r * D2 + lane * 4];
        float s = x.x * w1v.x + x.y * w1v.y + x.z * w1v.z + x.w * w1v.w;
#pragma unroll
        for (int o = 16; o; o >>= 1) s += __shfl_xor_sync(0xFFFFFFFFu, s, o);
        if (lane == 0) g_a1[b * TBODY + r] = s;
    }
    const float* pm = g_punM + (size_t)b * TPUN * D2;
    for (int r = warp; r < TPUN; r += 8) {
        float4 x = *(const float4*)&pm[(size_t)r * D2 + lane * 4];
        float s = x.x * w2v.x + x.y * w2v.y + x.z * w2v.z + x.w * w2v.w;
#pragma unroll
        for (int o = 16; o; o >>= 1) s += __shfl_xor_sync(0xFFFFFFFFu, s, o);
        if (lane == 0) g_a2[b * TPUN + r] = s;
    }
}

// ---------------- kernel 3: alignment maxes, 64x64 tiles, 4 blocks/SM -------------
#define ABK 16
__global__ void __launch_bounds__(256, 4) align_kernel(const float* __restrict__ w_u)
{
    int bx = blockIdx.x;
    int b  = bx >> 5;
    int tc = (bx >> 2) & 7;
    int pc = bx & 3;
    int t0 = tc * 64;
    int p0 = pc * 64;
    const float* bodyM = g_bodyM + (size_t)b * TBODY * D2;
    const float* punM  = g_punM  + (size_t)b * TPUN  * D2;

    __shared__ __align__(16) unsigned long long Bsu[2][ABK][66];
    __shared__ __align__(16) float Ps[2][ABK][68];
    __shared__ unsigned rms[64], cms[64];

    int tid = threadIdx.x;
    int tx = tid & 15, ty = tid >> 4;
    int q  = tid & 3;
    int rr = tid >> 2;

    if (tid < 64) { rms[tid] = 0u; cms[tid] = 0u; }

    unsigned long long acc[4][2];
#pragma unroll
    for (int i = 0; i < 4; i++) { acc[i][0] = 0ull; acc[i][1] = 0ull; }

    float4 bv, pv;
    {
        float4 w3v = *(const float4*)&w_u[2 * D2 + 4 * q];
        float4 v = *(const float4*)&bodyM[(size_t)(t0 + rr) * D2 + 4 * q];
        bv = make_float4(v.x * w3v.x, v.y * w3v.y, v.z * w3v.z, v.w * w3v.w);
        pv = *(const float4*)&punM[(size_t)(p0 + rr) * D2 + 4 * q];
    }

    for (int kc = 0; kc < 8; kc++) {
        int buf = kc & 1;
        Bsu[buf][4 * q + 0][rr] = pk2(bv.x);
        Bsu[buf][4 * q + 1][rr] = pk2(bv.y);
        Bsu[buf][4 * q + 2][rr] = pk2(bv.z);
        Bsu[buf][4 * q + 3][rr] = pk2(bv.w);
        Ps[buf][4 * q + 0][rr] = pv.x;
        Ps[buf][4 * q + 1][rr] = pv.y;
        Ps[buf][4 * q + 2][rr] = pv.z;
        Ps[buf][4 * q + 3][rr] = pv.w;
        __syncthreads();
        if (kc < 7) {
            int d0 = (kc + 1) * ABK;
            float4 w3v = *(const float4*)&w_u[2 * D2 + d0 + 4 * q];
            float4 v = *(const float4*)&bodyM[(size_t)(t0 + rr) * D2 + d0 + 4 * q];
            bv = make_float4(v.x * w3v.x, v.y * w3v.y, v.z * w3v.z, v.w * w3v.w);
            pv = *(const float4*)&punM[(size_t)(p0 + rr) * D2 + d0 + 4 * q];
        }
#pragma unroll
        for (int d = 0; d < ABK; d++) {
            ulonglong2 a01 = *(const ulonglong2*)&Bsu[buf][d][ty * 4];
            ulonglong2 a23 = *(const ulonglong2*)&Bsu[buf][d][ty * 4 + 2];
            ulonglong2 bb  = *(const ulonglong2*)&Ps[buf][d][tx * 4];
            acc[0][0] = ffma2(a01.x, bb.x, acc[0][0]);
            acc[0][1] = ffma2(a01.x, bb.y, acc[0][1]);
            acc[1][0] = ffma2(a01.y, bb.x, acc[1][0]);
            acc[1][1] = ffma2(a01.y, bb.y, acc[1][1]);
            acc[2][0] = ffma2(a23.x, bb.x, acc[2][0]);
            acc[2][1] = ffma2(a23.x, bb.y, acc[2][1]);
            acc[3][0] = ffma2(a23.y, bb.x, acc[3][0]);
            acc[3][1] = ffma2(a23.y, bb.y, acc[3][1]);
        }
    }

    float a2v[4];
#pragma unroll
    for (int j = 0; j < 4; j++) a2v[j] = g_a2[b * TPUN + p0 + tx * 4 + j];

    float cmax[4];
#pragma unroll
    for (int j = 0; j < 4; j++) cmax[j] = -1e30f;
#pragma unroll
    for (int i = 0; i < 4; i++) {
        float a1v = g_a1[b * TBODY + t0 + ty * 4 + i];
        float rmax = -1e30f;
#pragma unroll
        for (int j2 = 0; j2 < 2; j2++) {
            float2 v = up2(acc[i][j2]);
            float v0 = v.x + a1v + a2v[j2 * 2];
            float v1 = v.y + a1v + a2v[j2 * 2 + 1];
            rmax = fmaxf(rmax, fmaxf(v0, v1));
            cmax[j2 * 2]     = fmaxf(cmax[j2 * 2], v0);
            cmax[j2 * 2 + 1] = fmaxf(cmax[j2 * 2 + 1], v1);
        }
        atomicMax(&rms[ty * 4 + i], enc_f(rmax));
    }
#pragma unroll
    for (int j = 0; j < 4; j++)
        atomicMax(&cms[tx * 4 + j], enc_f(cmax[j]));
    __syncthreads();

    if (tid < 64) {
        atomicMax(&g_rowmax[b * TBODY + t0 + tid], rms[tid]);
        atomicMax(&g_colmax[b * TPUN + p0 + tid], cms[tid]);
    }
}

// ---------------- kernel 4: softmaxes + weighted sums + final linear (512 thr) ----
__global__ void __launch_bounds__(512) final_kernel(
    const float* __restrict__ Wd, const float* __restrict__ bd,
    float* __restrict__ outp)
{
    int b = blockIdx.x;
    int tid = threadIdx.x;
    int lane = tid & 31, warp = tid >> 5;   // 16 warps

    __shared__ float attb[TBODY];
    __shared__ float attp[TPUN];
    __shared__ float part[512];
    __shared__ float feat[G4];
    __shared__ float sred[16];

    float v = dec_f(g_rowmax[b * TBODY + tid]);
    float m = v;
#pragma unroll
    for (int o = 16; o; o >>= 1) m = fmaxf(m, __shfl_xor_sync(0xFFFFFFFFu, m, o));
    if (lane == 0) sred[warp] = m;
    __syncthreads();
    float M = sred[0];
#pragma unroll
    for (int w = 1; w < 16; w++) M = fmaxf(M, sred[w]);
    __syncthreads();
    float e = __expf(v - M);
    float ss = e;
#pragma unroll
    for (int o = 16; o; o >>= 1) ss += __shfl_xor_sync(0xFFFFFFFFu, ss, o);
    if (lane == 0) sred[warp] = ss;
    __syncthreads();
    float S = 0.f;
#pragma unroll
    for (int w = 0; w < 16; w++) S += sred[w];
    __syncthreads();
    attb[tid] = e / S;

    float u = (tid < TPUN) ? dec_f(g_colmax[b * TPUN + tid]) : -1e30f;
    float m2 = u;
#pragma unroll
    for (int o = 16; o; o >>= 1) m2 = fmaxf(m2, __shfl_xor_sync(0xFFFFFFFFu, m2, o));
    if (lane == 0) sred[warp] = m2;
    __syncthreads();
    float M2 = sred[0];
#pragma unroll
    for (int w = 1; w < 16; w++) M2 = fmaxf(M2, sred[w]);
    __syncthreads();
    float e2 = (tid < TPUN) ? __expf(u - M2) : 0.f;
    float ss2 = e2;
#pragma unroll
    for (int o = 16; o; o >>= 1) ss2 += __shfl_xor_sync(0xFFFFFFFFu, ss2, o);
    if (lane == 0) sred[warp] = ss2;
    __syncthreads();
    float S2 = 0.f;
#pragma unroll
    for (int w = 0; w < 16; w++) S2 += sred[w];
    if (tid < TPUN) attp[tid] = e2 / S2;
    __syncthreads();

    int col = tid & 255, half = tid >> 8;
    float s = 0.f;
    if (col < D2) {
        const float* bm = g_bodyM + (size_t)b * TBODY * D2 + col;
        int tbeg = half * 256, tend = tbeg + 256;
#pragma unroll 8
        for (int t = tbeg; t < tend; t++) s += bm[(size_t)t * D2] * attb[t];
    } else {
        int d = col - D2;
        const float* pm = g_punM + (size_t)b * TPUN * D2 + d;
        int pbeg = half * 128, pend = pbeg + 128;
#pragma unroll 8
        for (int p = pbeg; p < pend; p++) s += pm[(size_t)p * D2] * attp[p];
    }
    part[tid] = s;
    __syncthreads();
    if (tid < G4) feat[tid] = part[tid] + part[tid + 256];
    __syncthreads();

    if (tid < 3) {
        float sum = bd[tid];
        for (int k = 0; k < G4; k++) sum += feat[k] * Wd[tid * G4 + k];
        outp[b * 3 + tid] = sum;
    }
}

// ---------------- host launcher ----------------
extern "C" void kernel_launch(void* const* d_in, const int* in_sizes, int n_in,
                              void* d_out, int out_size)
{
    int base, iwu, iwd, ibd;
    if (in_sizes[3] == 76800) { base = 3; iwu = 15; iwd = 16; ibd = 17; }
    else                      { base = 6; iwu = 3;  iwd = 4;  ibd = 5;  }

    const int*   body_idx = (const int*)d_in[0];
    const int*   pun_idx  = (const int*)d_in[1];
    const float* emb      = (const float*)d_in[2];

    const float* Wih[4]; const float* Whh[4]; const float* bv[4];
    for (int s = 0; s < 4; s++) {
        Wih[s] = (const float*)d_in[base + 3 * s + 0];
        Whh[s] = (const float*)d_in[base + 3 * s + 1];
        bv[s]  = (const float*)d_in[base + 3 * s + 2];
    }
    const float* w_u = (const float*)d_in[iwu];
    const float* Wd  = (const float*)d_in[iwd];
    const float* bd  = (const float*)d_in[ibd];
    float* outp = (float*)d_out;

    zero_kernel<<<256, 256>>>();
    mark_kernel<<<(BATCH * (TBODY + TPUN)) / 256, 256>>>(body_idx, pun_idx);
    prep_wbf_kernel<<<1280, 256>>>(Wih[0], Wih[1], Wih[2], Wih[3]);

    dim3 ga(391, 2);
    aprep_kernel<<<ga, 256>>>(emb);

    dim3 gg((VOCAB + 127) / 128, 8, 2);
    gemm_tbl_wmma<<<gg, 256>>>(bv[0], bv[1], bv[2], bv[3]);

    lstm_kernel<<<512, 256>>>(body_idx, pun_idx, Whh[0], Whh[1], Whh[2], Whh[3]);

    aux_kernel<<<BATCH, 256>>>(w_u);

    align_kernel<<<BATCH * 32, 256>>>(w_u);

    final_kernel<<<BATCH, 512>>>(Wd, bd, outp);
    (void)n_in; (void)out_size;
}